// round 8
// baseline (speedup 1.0000x reference)
#include <cuda_runtime.h>
#include <cstdint>

// Problem constants
#define BATCH 4
#define CCH   256
#define NH    8
#define DH    32
#define NT    2304
#define O3    768
#define MT    256          // query tile (warp owns 32 rows = two m16 tiles)
#define KT    128          // key tile
#define NTILE (NT / KT)    // 18

// Scratch (allocation-free rule: __device__ globals)
__device__ float g_q  [BATCH * NH * NT * DH];  // tf32-rounded, pre-scaled
__device__ float g_k  [BATCH * NH * NT * DH];  // tf32-rounded
__device__ float g_v  [BATCH * NH * NT * DH];  // tf32-rounded
__device__ float g_aoh[BATCH * NT * CCH];      // attention out hi split
__device__ float g_aol[BATCH * NT * CCH];      // attention out lo split
__device__ float g_xh [BATCH * CCH * NT];      // x hi split  ([b,k,m] = x layout)
__device__ float g_xl [BATCH * CCH * NT];
__device__ float g_wqh[O3 * CCH];              // w_qkv splits
__device__ float g_wql[O3 * CCH];
__device__ float g_wph[CCH * CCH];             // w_proj splits
__device__ float g_wpl[CCH * CCH];

__device__ __forceinline__ uint32_t f2tf32(float f) {
    uint32_t r;
    asm("cvt.rna.tf32.f32 %0, %1;" : "=r"(r) : "f"(f));
    return r;
}
__device__ __forceinline__ void tf32_split_f(float f, float& hi, float& lo) {
    hi = __uint_as_float(f2tf32(f));
    lo = __uint_as_float(f2tf32(f - hi));
}
__device__ __forceinline__ uint32_t smem_u32(const void* p) {
    uint32_t a;
    asm("{ .reg .u64 t; cvta.to.shared.u64 t, %1; cvt.u32.u64 %0, t; }" : "=r"(a) : "l"(p));
    return a;
}
__device__ __forceinline__ void cp16(uint32_t dst, const void* src) {
    asm volatile("cp.async.cg.shared.global [%0], [%1], 16;" :: "r"(dst), "l"(src));
}
#define CP_COMMIT() asm volatile("cp.async.commit_group;" ::: "memory")
#define CP_WAIT1()  asm volatile("cp.async.wait_group 1;" ::: "memory")

__device__ __forceinline__ void mma_tf32(float c[4], const uint32_t a[4],
                                         uint32_t b0, uint32_t b1) {
    asm volatile(
        "mma.sync.aligned.m16n8k8.row.col.f32.tf32.tf32.f32 "
        "{%0,%1,%2,%3}, {%4,%5,%6,%7}, {%8,%9}, {%0,%1,%2,%3};"
        : "+f"(c[0]), "+f"(c[1]), "+f"(c[2]), "+f"(c[3])
        : "r"(a[0]), "r"(a[1]), "r"(a[2]), "r"(a[3]), "r"(b0), "r"(b1));
}

// ---------------------------------------------------------------------------
// Kernel 0: one-time hi/lo tf32 split of x, w_qkv, w_proj (memory-bound).
// ---------------------------------------------------------------------------
#define XN4 (BATCH * CCH * NT / 4)   // 589824
#define WQ4 (O3 * CCH / 4)           // 49152
#define WP4 (CCH * CCH / 4)          // 16384

__global__ __launch_bounds__(256) void split_kernel(
    const float* __restrict__ x, const float* __restrict__ wq,
    const float* __restrict__ wp)
{
    int i = blockIdx.x * 256 + threadIdx.x;
    const float4* src;
    float4 *dh, *dl;
    int j;
    if (i < XN4)                   { src = (const float4*)x;  dh = (float4*)g_xh;  dl = (float4*)g_xl;  j = i; }
    else if (i < XN4 + WQ4)        { src = (const float4*)wq; dh = (float4*)g_wqh; dl = (float4*)g_wql; j = i - XN4; }
    else if (i < XN4 + WQ4 + WP4)  { src = (const float4*)wp; dh = (float4*)g_wph; dl = (float4*)g_wpl; j = i - XN4 - WQ4; }
    else return;
    float4 f = src[j];
    float4 h, l;
    tf32_split_f(f.x, h.x, l.x); tf32_split_f(f.y, h.y, l.y);
    tf32_split_f(f.z, h.z, l.z); tf32_split_f(f.w, h.w, l.w);
    dh[j] = h; dl[j] = l;
}

// ---------------------------------------------------------------------------
// Kernel 1: QKV projection, tf32x3 GEMM, cp.async double-buffered, zero
//   conversions in the hot loop (pre-split inputs).
//   Stage: Ah[16][136] Al[16][136] Bh[64][20] Bl[64][20] = 6912 words.
// ---------------------------------------------------------------------------
#define QKV_STAGE_W 6912

__global__ __launch_bounds__(256, 2) void qkv_tc_kernel(const float* __restrict__ bias)
{
    extern __shared__ uint32_t ds[];
    const uint32_t sb = smem_u32(ds);

    const int b  = blockIdx.z;
    const int m0 = blockIdx.x * 128;
    const int o0 = blockIdx.y * 64;
    const int tid  = threadIdx.x;
    const int wid  = tid >> 5;
    const int lane = tid & 31;
    const int gq   = lane >> 2;
    const int t4   = lane & 3;
    const int wm   = wid & 3, wn = wid >> 2;

    const int akk = tid >> 4, amm = (tid & 15) * 8;
    const int boo = tid >> 2, bkk = (tid & 3) * 4;

    const float* xh = g_xh + (size_t)b * CCH * NT;
    const float* xl = g_xl + (size_t)b * CCH * NT;

    const uint32_t a_off = (uint32_t)(akk * 136 + amm) * 4;
    const uint32_t b_off = (uint32_t)(boo * 20 + bkk) * 4;

    // prologue: stage 0
    {
        const uint32_t base = sb;
        cp16(base + a_off,                  xh + (size_t)akk * NT + m0 + amm);
        cp16(base + a_off + 16,             xh + (size_t)akk * NT + m0 + amm + 4);
        cp16(base + 2176 * 4 + a_off,       xl + (size_t)akk * NT + m0 + amm);
        cp16(base + 2176 * 4 + a_off + 16,  xl + (size_t)akk * NT + m0 + amm + 4);
        cp16(base + 4352 * 4 + b_off,       g_wqh + (size_t)(o0 + boo) * CCH + bkk);
        cp16(base + 5632 * 4 + b_off,       g_wql + (size_t)(o0 + boo) * CCH + bkk);
    }
    CP_COMMIT();

    float c[2][4][4] = {};

    for (int it = 0; it < 16; it++) {
        if (it + 1 < 16) {
            const int k0 = (it + 1) * 16;
            const uint32_t base = sb + ((it + 1) & 1) * QKV_STAGE_W * 4;
            cp16(base + a_off,                  xh + (size_t)(k0 + akk) * NT + m0 + amm);
            cp16(base + a_off + 16,             xh + (size_t)(k0 + akk) * NT + m0 + amm + 4);
            cp16(base + 2176 * 4 + a_off,       xl + (size_t)(k0 + akk) * NT + m0 + amm);
            cp16(base + 2176 * 4 + a_off + 16,  xl + (size_t)(k0 + akk) * NT + m0 + amm + 4);
            cp16(base + 4352 * 4 + b_off,       g_wqh + (size_t)(o0 + boo) * CCH + k0 + bkk);
            cp16(base + 5632 * 4 + b_off,       g_wql + (size_t)(o0 + boo) * CCH + k0 + bkk);
        }
        CP_COMMIT();
        CP_WAIT1();
        __syncthreads();

        const uint32_t* Ah = ds + (it & 1) * QKV_STAGE_W;
        const uint32_t* Al = Ah + 2176;
        const uint32_t* Bh = Ah + 4352;
        const uint32_t* Bl = Ah + 5632;
        #pragma unroll
        for (int kc = 0; kc < 2; kc++) {
            const int kb = kc * 8;
            uint32_t ah[2][4], al[2][4], bh[4][2], bl[4][2];
            #pragma unroll
            for (int mt = 0; mt < 2; mt++) {
                int m = wm * 32 + mt * 16 + gq;
                ah[mt][0] = Ah[(kb + t4) * 136 + m];
                al[mt][0] = Al[(kb + t4) * 136 + m];
                ah[mt][1] = Ah[(kb + t4) * 136 + m + 8];
                al[mt][1] = Al[(kb + t4) * 136 + m + 8];
                ah[mt][2] = Ah[(kb + t4 + 4) * 136 + m];
                al[mt][2] = Al[(kb + t4 + 4) * 136 + m];
                ah[mt][3] = Ah[(kb + t4 + 4) * 136 + m + 8];
                al[mt][3] = Al[(kb + t4 + 4) * 136 + m + 8];
            }
            #pragma unroll
            for (int nt = 0; nt < 4; nt++) {
                int n = wn * 32 + nt * 8 + gq;
                bh[nt][0] = Bh[n * 20 + kb + t4];
                bh[nt][1] = Bh[n * 20 + kb + t4 + 4];
                bl[nt][0] = Bl[n * 20 + kb + t4];
                bl[nt][1] = Bl[n * 20 + kb + t4 + 4];
            }
            #pragma unroll
            for (int mt = 0; mt < 2; mt++)
                #pragma unroll
                for (int nt = 0; nt < 4; nt++) {
                    mma_tf32(c[mt][nt], ah[mt], bl[nt][0], bl[nt][1]);
                    mma_tf32(c[mt][nt], al[mt], bh[nt][0], bh[nt][1]);
                    mma_tf32(c[mt][nt], ah[mt], bh[nt][0], bh[nt][1]);
                }
        }
        __syncthreads();
    }

    // epilogue: bias, then tf32-round q (post-scale), k, v so the attention
    // kernel's MMA truncation is exact (cp.async stages rounded values).
    const float scale = 0.17677669529663687f;  // 32^-0.5
    #pragma unroll
    for (int mt = 0; mt < 2; mt++)
        #pragma unroll
        for (int nt = 0; nt < 4; nt++)
            #pragma unroll
            for (int i = 0; i < 4; i++) {
                int m = m0 + wm * 32 + mt * 16 + gq + ((i >= 2) ? 8 : 0);
                int o = o0 + wn * 32 + nt * 8 + 2 * t4 + (i & 1);
                float val = c[mt][nt][i] + __ldg(bias + o);
                int kind = o / CCH;
                int oc = o % CCH;
                int h = oc / DH, d = oc % DH;
                int idx = ((b * NH + h) * NT + m) * DH + d;
                if (kind == 0)
                    g_q[idx] = __uint_as_float(f2tf32(val * scale));
                else if (kind == 1)
                    g_k[idx] = __uint_as_float(f2tf32(val));
                else
                    g_v[idx] = __uint_as_float(f2tf32(val));
            }
}

// ---------------------------------------------------------------------------
// Kernel 2: tf32 mma.sync flash attention, MT=256, cp.async double-buffered.
//   K/V are pre-rounded to tf32 by the qkv epilogue, so staging raw bits is
//   exact. Output written as hi/lo splits for the proj kernel.
// ---------------------------------------------------------------------------
#define KSTR 36
#define VSTR 40
#define ATT_STAGE_W (KT * KSTR + KT * VSTR)   // 9728 words
#define ATT_SMEM    (2 * ATT_STAGE_W * 4)     // 77824 B

__global__ __launch_bounds__(256, 2) void attn_mma_kernel()
{
    extern __shared__ float smf[];
    const uint32_t smbase = smem_u32(smf);

    const int bh   = blockIdx.y;
    const int n0   = blockIdx.x * MT;
    const int tid  = threadIdx.x;
    const int wid  = tid >> 5;
    const int lane = tid & 31;
    const int gq   = lane >> 2;
    const int t4   = lane & 3;
    const int r0   = wid * 32 + gq;

    const int srow = tid >> 1;
    const int half = tid & 1;
    const int si   = srow & 7;
    const int prow = (srow & ~7) | ((si & 3) * 2) | (si >> 2);
    const float* kbase = g_k + ((size_t)bh * NT + srow) * DH + half * 16;
    const float* vbase = g_v + ((size_t)bh * NT + srow) * DH + half * 16;

    // Q fragments: g_q is already tf32-rounded — raw bit loads
    uint32_t qa[2][4][4];
    #pragma unroll
    for (int mt = 0; mt < 2; mt++) {
        const float* Q0 = g_q + ((size_t)bh * NT + n0 + r0 + mt * 16) * DH;
        const float* Q8 = Q0 + 8 * DH;
        #pragma unroll
        for (int kc = 0; kc < 4; kc++) {
            qa[mt][kc][0] = __float_as_uint(Q0[kc * 8 + t4]);
            qa[mt][kc][1] = __float_as_uint(Q8[kc * 8 + t4]);
            qa[mt][kc][2] = __float_as_uint(Q0[kc * 8 + t4 + 4]);
            qa[mt][kc][3] = __float_as_uint(Q8[kc * 8 + t4 + 4]);
        }
    }

    float o[2][4][4] = {};
    float l00 = 0.f, l01 = 0.f, l10 = 0.f, l11 = 0.f;

    {
        uint32_t kdst = smbase + (prow * KSTR + half * 16) * 4;
        uint32_t vdst = smbase + (KT * KSTR + srow * VSTR + half * 16) * 4;
        #pragma unroll
        for (int cv = 0; cv < 4; cv++) {
            cp16(kdst + cv * 16, kbase + cv * 4);
            cp16(vdst + cv * 16, vbase + cv * 4);
        }
    }
    CP_COMMIT();

    for (int t = 0; t < NTILE; t++) {
        if (t + 1 < NTILE) {
            const int bs = (t + 1) & 1;
            uint32_t kdst = smbase + (bs * ATT_STAGE_W + prow * KSTR + half * 16) * 4;
            uint32_t vdst = smbase + (bs * ATT_STAGE_W + KT * KSTR + srow * VSTR + half * 16) * 4;
            const float* ks = kbase + (size_t)(t + 1) * KT * DH;
            const float* vs = vbase + (size_t)(t + 1) * KT * DH;
            #pragma unroll
            for (int cv = 0; cv < 4; cv++) {
                cp16(kdst + cv * 16, ks + cv * 4);
                cp16(vdst + cv * 16, vs + cv * 4);
            }
        }
        CP_COMMIT();
        CP_WAIT1();
        __syncthreads();

        const float* Ks = smf + (t & 1) * ATT_STAGE_W;
        const float* Vs = Ks + KT * KSTR;

        #pragma unroll 2
        for (int nt = 0; nt < 16; nt++) {
            uint32_t kf[8];
            const uint32_t* kb = (const uint32_t*)(Ks + (nt * 8 + gq) * KSTR + t4);
            #pragma unroll
            for (int kc = 0; kc < 4; kc++) {
                kf[2 * kc]     = kb[kc * 8];
                kf[2 * kc + 1] = kb[kc * 8 + 4];
            }
            float s0[4] = {}, s1[4] = {};
            #pragma unroll
            for (int kc = 0; kc < 4; kc++) {
                mma_tf32(s0, qa[0][kc], kf[2 * kc], kf[2 * kc + 1]);
                mma_tf32(s1, qa[1][kc], kf[2 * kc], kf[2 * kc + 1]);
            }

            float e00 = __expf(s0[0]), e01 = __expf(s0[1]);
            float e02 = __expf(s0[2]), e03 = __expf(s0[3]);
            float e10 = __expf(s1[0]), e11 = __expf(s1[1]);
            float e12 = __expf(s1[2]), e13 = __expf(s1[3]);
            l00 += e00 + e01; l01 += e02 + e03;
            l10 += e10 + e11; l11 += e12 + e13;
            uint32_t pa0[4] = { f2tf32(e00), f2tf32(e02), f2tf32(e01), f2tf32(e03) };
            uint32_t pa1[4] = { f2tf32(e10), f2tf32(e12), f2tf32(e11), f2tf32(e13) };

            uint32_t vf[8];
            const uint32_t* vb0 = (const uint32_t*)(Vs + (nt * 8 + t4) * VSTR + gq);
            const uint32_t* vb1 = vb0 + 4 * VSTR;
            #pragma unroll
            for (int no = 0; no < 4; no++) {
                vf[2 * no]     = vb0[no * 8];
                vf[2 * no + 1] = vb1[no * 8];
            }
            #pragma unroll
            for (int no = 0; no < 4; no++) {
                mma_tf32(o[0][no], pa0, vf[2 * no], vf[2 * no + 1]);
                mma_tf32(o[1][no], pa1, vf[2 * no], vf[2 * no + 1]);
            }
        }
        __syncthreads();
    }

    l00 += __shfl_xor_sync(0xFFFFFFFFu, l00, 1);
    l00 += __shfl_xor_sync(0xFFFFFFFFu, l00, 2);
    l01 += __shfl_xor_sync(0xFFFFFFFFu, l01, 1);
    l01 += __shfl_xor_sync(0xFFFFFFFFu, l01, 2);
    l10 += __shfl_xor_sync(0xFFFFFFFFu, l10, 1);
    l10 += __shfl_xor_sync(0xFFFFFFFFu, l10, 2);
    l11 += __shfl_xor_sync(0xFFFFFFFFu, l11, 1);
    l11 += __shfl_xor_sync(0xFFFFFFFFu, l11, 2);

    const int b = bh >> 3, h = bh & 7;
    #pragma unroll
    for (int mt = 0; mt < 2; mt++) {
        float i0 = 1.f / (mt ? l10 : l00);
        float i1 = 1.f / (mt ? l11 : l01);
        size_t off0 = ((size_t)(b * NT) + n0 + r0 + mt * 16) * CCH + h * DH;
        size_t off8 = off0 + 8 * CCH;
        #pragma unroll
        for (int no = 0; no < 4; no++) {
            int d = no * 8 + 2 * t4;
            float a0 = o[mt][no][0] * i0, a1 = o[mt][no][1] * i0;
            float a2 = o[mt][no][2] * i1, a3 = o[mt][no][3] * i1;
            float h0, l0f, h1, l1f, h2, l2f, h3, l3f;
            tf32_split_f(a0, h0, l0f); tf32_split_f(a1, h1, l1f);
            tf32_split_f(a2, h2, l2f); tf32_split_f(a3, h3, l3f);
            *(float2*)(g_aoh + off0 + d) = make_float2(h0, h1);
            *(float2*)(g_aol + off0 + d) = make_float2(l0f, l1f);
            *(float2*)(g_aoh + off8 + d) = make_float2(h2, h3);
            *(float2*)(g_aol + off8 + d) = make_float2(l2f, l3f);
        }
    }
}

// ---------------------------------------------------------------------------
// Kernel 3: output projection, tf32x3 GEMM, cp.async double-buffered, zero
//   conversions (A pre-split by attention, B pre-split by split_kernel).
//   Stage: Ah[128][20] Al[128][20] Bh[64][20] Bl[64][20] = 7680 words.
// ---------------------------------------------------------------------------
#define PROJ_STAGE_W 7680

__global__ __launch_bounds__(256, 2) void proj_tc_kernel(
    const float* __restrict__ bias, float* __restrict__ out)
{
    extern __shared__ uint32_t dp[];
    const uint32_t sb = smem_u32(dp);

    const int b  = blockIdx.z;
    const int m0 = blockIdx.x * 128;
    const int o0 = blockIdx.y * 64;
    const int tid  = threadIdx.x;
    const int wid  = tid >> 5;
    const int lane = tid & 31;
    const int gq   = lane >> 2;
    const int t4   = lane & 3;
    const int wm   = wid & 3, wn = wid >> 2;

    const int amm = tid >> 1, akk = (tid & 1) * 8;
    const int boo = tid >> 2, bkk = (tid & 3) * 4;

    const float* ah_g = g_aoh + (size_t)b * NT * CCH;
    const float* al_g = g_aol + (size_t)b * NT * CCH;

    const uint32_t a_off = (uint32_t)(amm * 20 + akk) * 4;
    const uint32_t b_off = (uint32_t)(boo * 20 + bkk) * 4;

    {
        const uint32_t base = sb;
        cp16(base + a_off,                  ah_g + (size_t)(m0 + amm) * CCH + akk);
        cp16(base + a_off + 16,             ah_g + (size_t)(m0 + amm) * CCH + akk + 4);
        cp16(base + 2560 * 4 + a_off,       al_g + (size_t)(m0 + amm) * CCH + akk);
        cp16(base + 2560 * 4 + a_off + 16,  al_g + (size_t)(m0 + amm) * CCH + akk + 4);
        cp16(base + 5120 * 4 + b_off,       g_wph + (size_t)(o0 + boo) * CCH + bkk);
        cp16(base + 6400 * 4 + b_off,       g_wpl + (size_t)(o0 + boo) * CCH + bkk);
    }
    CP_COMMIT();

    float c[2][4][4] = {};

    for (int it = 0; it < 16; it++) {
        if (it + 1 < 16) {
            const int k0 = (it + 1) * 16;
            const uint32_t base = sb + ((it + 1) & 1) * PROJ_STAGE_W * 4;
            cp16(base + a_off,                  ah_g + (size_t)(m0 + amm) * CCH + k0 + akk);
            cp16(base + a_off + 16,             ah_g + (size_t)(m0 + amm) * CCH + k0 + akk + 4);
            cp16(base + 2560 * 4 + a_off,       al_g + (size_t)(m0 + amm) * CCH + k0 + akk);
            cp16(base + 2560 * 4 + a_off + 16,  al_g + (size_t)(m0 + amm) * CCH + k0 + akk + 4);
            cp16(base + 5120 * 4 + b_off,       g_wph + (size_t)(o0 + boo) * CCH + k0 + bkk);
            cp16(base + 6400 * 4 + b_off,       g_wpl + (size_t)(o0 + boo) * CCH + k0 + bkk);
        }
        CP_COMMIT();
        CP_WAIT1();
        __syncthreads();

        const uint32_t* Ah = dp + (it & 1) * PROJ_STAGE_W;
        const uint32_t* Al = Ah + 2560;
        const uint32_t* Bh = Ah + 5120;
        const uint32_t* Bl = Ah + 6400;
        #pragma unroll
        for (int kc = 0; kc < 2; kc++) {
            const int kb = kc * 8;
            uint32_t ah[2][4], al[2][4], bh[4][2], bl[4][2];
            #pragma unroll
            for (int mt = 0; mt < 2; mt++) {
                int m = wm * 32 + mt * 16 + gq;
                ah[mt][0] = Ah[m * 20 + kb + t4];
                al[mt][0] = Al[m * 20 + kb + t4];
                ah[mt][1] = Ah[(m + 8) * 20 + kb + t4];
                al[mt][1] = Al[(m + 8) * 20 + kb + t4];
                ah[mt][2] = Ah[m * 20 + kb + t4 + 4];
                al[mt][2] = Al[m * 20 + kb + t4 + 4];
                ah[mt][3] = Ah[(m + 8) * 20 + kb + t4 + 4];
                al[mt][3] = Al[(m + 8) * 20 + kb + t4 + 4];
            }
            #pragma unroll
            for (int nt = 0; nt < 4; nt++) {
                int n = wn * 32 + nt * 8 + gq;
                bh[nt][0] = Bh[n * 20 + kb + t4];
                bh[nt][1] = Bh[n * 20 + kb + t4 + 4];
                bl[nt][0] = Bl[n * 20 + kb + t4];
                bl[nt][1] = Bl[n * 20 + kb + t4 + 4];
            }
            #pragma unroll
            for (int mt = 0; mt < 2; mt++)
                #pragma unroll
                for (int nt = 0; nt < 4; nt++) {
                    mma_tf32(c[mt][nt], ah[mt], bl[nt][0], bl[nt][1]);
                    mma_tf32(c[mt][nt], al[mt], bh[nt][0], bh[nt][1]);
                    mma_tf32(c[mt][nt], ah[mt], bh[nt][0], bh[nt][1]);
                }
        }
        __syncthreads();
    }

    #pragma unroll
    for (int mt = 0; mt < 2; mt++)
        #pragma unroll
        for (int nt = 0; nt < 4; nt++)
            #pragma unroll
            for (int i = 0; i < 4; i++) {
                int m = m0 + wm * 32 + mt * 16 + gq + ((i >= 2) ? 8 : 0);
                int o = o0 + wn * 32 + nt * 8 + 2 * t4 + (i & 1);
                out[(size_t)b * CCH * NT + (size_t)o * NT + m] =
                    c[mt][nt][i] + __ldg(bias + o);
            }
}

// ---------------------------------------------------------------------------
extern "C" void kernel_launch(void* const* d_in, const int* in_sizes, int n_in,
                              void* d_out, int out_size)
{
    (void)in_sizes; (void)n_in; (void)out_size;
    const float* x      = (const float*)d_in[0];
    const float* w_qkv  = (const float*)d_in[1];
    const float* b_qkv  = (const float*)d_in[2];
    const float* w_proj = (const float*)d_in[3];
    const float* b_proj = (const float*)d_in[4];
    float* out = (float*)d_out;

    cudaFuncSetAttribute(qkv_tc_kernel,
                         cudaFuncAttributeMaxDynamicSharedMemorySize,
                         2 * QKV_STAGE_W * 4);
    cudaFuncSetAttribute(attn_mma_kernel,
                         cudaFuncAttributeMaxDynamicSharedMemorySize, ATT_SMEM);
    cudaFuncSetAttribute(proj_tc_kernel,
                         cudaFuncAttributeMaxDynamicSharedMemorySize,
                         2 * PROJ_STAGE_W * 4);

    split_kernel<<<(XN4 + WQ4 + WP4 + 255) / 256, 256>>>(x, w_qkv, w_proj);

    dim3 g1(NT / 128, O3 / 64, BATCH);
    qkv_tc_kernel<<<g1, 256, 2 * QKV_STAGE_W * 4>>>(b_qkv);

    dim3 g2(NT / MT, BATCH * NH);
    attn_mma_kernel<<<g2, 256, ATT_SMEM>>>();

    dim3 g3(NT / 128, CCH / 64, BATCH);
    proj_tc_kernel<<<g3, 256, 2 * PROJ_STAGE_W * 4>>>(b_proj, out);
}

// round 9
// speedup vs baseline: 1.1733x; 1.1733x over previous
#include <cuda_runtime.h>
#include <cstdint>

// Problem constants
#define BATCH 4
#define CCH   256
#define NH    8
#define DH    32
#define NT    2304
#define O3    768
#define MT    256
#define KT    128
#define NTILE (NT / KT)    // 18

// Scratch (allocation-free rule: __device__ globals)
__device__ float g_q  [BATCH * NH * NT * DH];  // tf32-rounded, pre-scaled
__device__ float g_k  [BATCH * NH * NT * DH];  // tf32-rounded
__device__ float g_v  [BATCH * NH * NT * DH];  // tf32-rounded
__device__ float g_aoh[BATCH * NT * CCH];      // attention out hi split
__device__ float g_aol[BATCH * NT * CCH];      // attention out lo split
__device__ float g_xr [BATCH * CCH * NT];      // x, tf32-RNA-rounded
__device__ float g_wqr[O3 * CCH];              // w_qkv, tf32-RNA-rounded
__device__ float g_wph[CCH * CCH];             // w_proj hi/lo splits
__device__ float g_wpl[CCH * CCH];

__device__ __forceinline__ uint32_t f2tf32(float f) {
    uint32_t r;
    asm("cvt.rna.tf32.f32 %0, %1;" : "=r"(r) : "f"(f));
    return r;
}
__device__ __forceinline__ void tf32_split_f(float f, float& hi, float& lo) {
    hi = __uint_as_float(f2tf32(f));
    lo = __uint_as_float(f2tf32(f - hi));
}
__device__ __forceinline__ uint32_t smem_u32(const void* p) {
    uint32_t a;
    asm("{ .reg .u64 t; cvta.to.shared.u64 t, %1; cvt.u32.u64 %0, t; }" : "=r"(a) : "l"(p));
    return a;
}
__device__ __forceinline__ void cp16(uint32_t dst, const void* src) {
    asm volatile("cp.async.cg.shared.global [%0], [%1], 16;" :: "r"(dst), "l"(src));
}
#define CP_COMMIT() asm volatile("cp.async.commit_group;" ::: "memory")
#define CP_WAIT1()  asm volatile("cp.async.wait_group 1;" ::: "memory")

__device__ __forceinline__ void mma_tf32(float c[4], const uint32_t a[4],
                                         uint32_t b0, uint32_t b1) {
    asm volatile(
        "mma.sync.aligned.m16n8k8.row.col.f32.tf32.tf32.f32 "
        "{%0,%1,%2,%3}, {%4,%5,%6,%7}, {%8,%9}, {%0,%1,%2,%3};"
        : "+f"(c[0]), "+f"(c[1]), "+f"(c[2]), "+f"(c[3])
        : "r"(a[0]), "r"(a[1]), "r"(a[2]), "r"(a[3]), "r"(b0), "r"(b1));
}

// ---------------------------------------------------------------------------
// Kernel 0: prep — RNA-round x and w_qkv to tf32; hi/lo split w_proj.
// ---------------------------------------------------------------------------
#define XN4 (BATCH * CCH * NT / 4)   // 589824
#define WQ4 (O3 * CCH / 4)           // 49152
#define WP4 (CCH * CCH / 4)          // 16384

__global__ __launch_bounds__(256) void split_kernel(
    const float* __restrict__ x, const float* __restrict__ wq,
    const float* __restrict__ wp)
{
    int i = blockIdx.x * 256 + threadIdx.x;
    if (i < XN4) {
        float4 f = ((const float4*)x)[i];
        uint4 u = make_uint4(f2tf32(f.x), f2tf32(f.y), f2tf32(f.z), f2tf32(f.w));
        ((uint4*)g_xr)[i] = u;
    } else if (i < XN4 + WQ4) {
        int j = i - XN4;
        float4 f = ((const float4*)wq)[j];
        uint4 u = make_uint4(f2tf32(f.x), f2tf32(f.y), f2tf32(f.z), f2tf32(f.w));
        ((uint4*)g_wqr)[j] = u;
    } else if (i < XN4 + WQ4 + WP4) {
        int j = i - XN4 - WQ4;
        float4 f = ((const float4*)wp)[j];
        float4 h, l;
        tf32_split_f(f.x, h.x, l.x); tf32_split_f(f.y, h.y, l.y);
        tf32_split_f(f.z, h.z, l.z); tf32_split_f(f.w, h.w, l.w);
        ((float4*)g_wph)[j] = h; ((float4*)g_wpl)[j] = l;
    }
}

// ---------------------------------------------------------------------------
// Kernel 1: QKV projection, SINGLE-tf32 GEMM (output is tf32-rounded anyway),
//   BK=32 (8 iters), cp.async double-buffered, zero in-loop conversions.
//   Stage: A[32][136] ([k][m]) + B[64][36] ([n][k]) = 6656 words = 26.6 KB.
// ---------------------------------------------------------------------------
#define QKV_STAGE_W 6656

__global__ __launch_bounds__(256, 3) void qkv_tc_kernel(const float* __restrict__ bias)
{
    extern __shared__ uint32_t ds[];
    const uint32_t sb = smem_u32(ds);

    const int b  = blockIdx.z;
    const int m0 = blockIdx.x * 128;
    const int o0 = blockIdx.y * 64;
    const int tid  = threadIdx.x;
    const int wid  = tid >> 5;
    const int lane = tid & 31;
    const int gq   = lane >> 2;
    const int t4   = lane & 3;
    const int wm   = wid & 3, wn = wid >> 2;

    // staging coords: A 32 rows x 128 floats (8 thr/row, 16 floats each),
    //                 B 64 rows x 32 floats (4 thr/row, 8 floats each)
    const int akk = tid >> 3, amm = (tid & 7) * 16;
    const int boo = tid >> 2, bkk = (tid & 3) * 8;

    const float* xr = g_xr + (size_t)b * CCH * NT;
    const uint32_t a_off = (uint32_t)(akk * 136 + amm) * 4;
    const uint32_t b_off = (uint32_t)(4352 + boo * 36 + bkk) * 4;

    // prologue: stage 0
    {
        const float* as = xr + (size_t)akk * NT + m0 + amm;
        #pragma unroll
        for (int cv = 0; cv < 4; cv++) cp16(sb + a_off + cv * 16, as + cv * 4);
        const float* bs = g_wqr + (size_t)(o0 + boo) * CCH + bkk;
        cp16(sb + b_off, bs);
        cp16(sb + b_off + 16, bs + 4);
    }
    CP_COMMIT();

    float c[2][4][4] = {};

    for (int it = 0; it < 8; it++) {
        if (it + 1 < 8) {
            const int k0 = (it + 1) * 32;
            const uint32_t base = sb + ((it + 1) & 1) * QKV_STAGE_W * 4;
            const float* as = xr + (size_t)(k0 + akk) * NT + m0 + amm;
            #pragma unroll
            for (int cv = 0; cv < 4; cv++) cp16(base + a_off + cv * 16, as + cv * 4);
            const float* bs = g_wqr + (size_t)(o0 + boo) * CCH + k0 + bkk;
            cp16(base + b_off, bs);
            cp16(base + b_off + 16, bs + 4);
        }
        CP_COMMIT();
        CP_WAIT1();
        __syncthreads();

        const uint32_t* A = ds + (it & 1) * QKV_STAGE_W;
        const uint32_t* B = A + 4352;
        #pragma unroll
        for (int kc = 0; kc < 4; kc++) {
            const int kb = kc * 8;
            uint32_t ah[2][4], bh[4][2];
            #pragma unroll
            for (int mt = 0; mt < 2; mt++) {
                int m = wm * 32 + mt * 16 + gq;
                ah[mt][0] = A[(kb + t4) * 136 + m];
                ah[mt][1] = A[(kb + t4) * 136 + m + 8];
                ah[mt][2] = A[(kb + t4 + 4) * 136 + m];
                ah[mt][3] = A[(kb + t4 + 4) * 136 + m + 8];
            }
            #pragma unroll
            for (int nt = 0; nt < 4; nt++) {
                int n = wn * 32 + nt * 8 + gq;
                bh[nt][0] = B[n * 36 + kb + t4];
                bh[nt][1] = B[n * 36 + kb + t4 + 4];
            }
            #pragma unroll
            for (int mt = 0; mt < 2; mt++)
                #pragma unroll
                for (int nt = 0; nt < 4; nt++)
                    mma_tf32(c[mt][nt], ah[mt], bh[nt][0], bh[nt][1]);
        }
        __syncthreads();
    }

    // epilogue: bias, tf32-round q (post-scale), k, v
    const float scale = 0.17677669529663687f;  // 32^-0.5
    #pragma unroll
    for (int mt = 0; mt < 2; mt++)
        #pragma unroll
        for (int nt = 0; nt < 4; nt++)
            #pragma unroll
            for (int i = 0; i < 4; i++) {
                int m = m0 + wm * 32 + mt * 16 + gq + ((i >= 2) ? 8 : 0);
                int o = o0 + wn * 32 + nt * 8 + 2 * t4 + (i & 1);
                float val = c[mt][nt][i] + __ldg(bias + o);
                int kind = o / CCH;
                int oc = o % CCH;
                int h = oc / DH, d = oc % DH;
                int idx = ((b * NH + h) * NT + m) * DH + d;
                if (kind == 0)
                    g_q[idx] = __uint_as_float(f2tf32(val * scale));
                else if (kind == 1)
                    g_k[idx] = __uint_as_float(f2tf32(val));
                else
                    g_v[idx] = __uint_as_float(f2tf32(val));
            }
}

// ---------------------------------------------------------------------------
// Kernel 2: tf32 mma.sync flash attention, MT=256, cp.async double-buffered.
//   K/V pre-rounded to tf32 by qkv epilogue (staging raw bits is exact).
//   Output written as hi/lo splits for proj. (Unchanged from R8.)
// ---------------------------------------------------------------------------
#define KSTR 36
#define VSTR 40
#define ATT_STAGE_W (KT * KSTR + KT * VSTR)
#define ATT_SMEM    (2 * ATT_STAGE_W * 4)

__global__ __launch_bounds__(256, 2) void attn_mma_kernel()
{
    extern __shared__ float smf[];
    const uint32_t smbase = smem_u32(smf);

    const int bh   = blockIdx.y;
    const int n0   = blockIdx.x * MT;
    const int tid  = threadIdx.x;
    const int wid  = tid >> 5;
    const int lane = tid & 31;
    const int gq   = lane >> 2;
    const int t4   = lane & 3;
    const int r0   = wid * 32 + gq;

    const int srow = tid >> 1;
    const int half = tid & 1;
    const int si   = srow & 7;
    const int prow = (srow & ~7) | ((si & 3) * 2) | (si >> 2);
    const float* kbase = g_k + ((size_t)bh * NT + srow) * DH + half * 16;
    const float* vbase = g_v + ((size_t)bh * NT + srow) * DH + half * 16;

    uint32_t qa[2][4][4];
    #pragma unroll
    for (int mt = 0; mt < 2; mt++) {
        const float* Q0 = g_q + ((size_t)bh * NT + n0 + r0 + mt * 16) * DH;
        const float* Q8 = Q0 + 8 * DH;
        #pragma unroll
        for (int kc = 0; kc < 4; kc++) {
            qa[mt][kc][0] = __float_as_uint(Q0[kc * 8 + t4]);
            qa[mt][kc][1] = __float_as_uint(Q8[kc * 8 + t4]);
            qa[mt][kc][2] = __float_as_uint(Q0[kc * 8 + t4 + 4]);
            qa[mt][kc][3] = __float_as_uint(Q8[kc * 8 + t4 + 4]);
        }
    }

    float o[2][4][4] = {};
    float l00 = 0.f, l01 = 0.f, l10 = 0.f, l11 = 0.f;

    {
        uint32_t kdst = smbase + (prow * KSTR + half * 16) * 4;
        uint32_t vdst = smbase + (KT * KSTR + srow * VSTR + half * 16) * 4;
        #pragma unroll
        for (int cv = 0; cv < 4; cv++) {
            cp16(kdst + cv * 16, kbase + cv * 4);
            cp16(vdst + cv * 16, vbase + cv * 4);
        }
    }
    CP_COMMIT();

    for (int t = 0; t < NTILE; t++) {
        if (t + 1 < NTILE) {
            const int bs = (t + 1) & 1;
            uint32_t kdst = smbase + (bs * ATT_STAGE_W + prow * KSTR + half * 16) * 4;
            uint32_t vdst = smbase + (bs * ATT_STAGE_W + KT * KSTR + srow * VSTR + half * 16) * 4;
            const float* ks = kbase + (size_t)(t + 1) * KT * DH;
            const float* vs = vbase + (size_t)(t + 1) * KT * DH;
            #pragma unroll
            for (int cv = 0; cv < 4; cv++) {
                cp16(kdst + cv * 16, ks + cv * 4);
                cp16(vdst + cv * 16, vs + cv * 4);
            }
        }
        CP_COMMIT();
        CP_WAIT1();
        __syncthreads();

        const float* Ks = smf + (t & 1) * ATT_STAGE_W;
        const float* Vs = Ks + KT * KSTR;

        #pragma unroll 2
        for (int nt = 0; nt < 16; nt++) {
            uint32_t kf[8];
            const uint32_t* kb = (const uint32_t*)(Ks + (nt * 8 + gq) * KSTR + t4);
            #pragma unroll
            for (int kc = 0; kc < 4; kc++) {
                kf[2 * kc]     = kb[kc * 8];
                kf[2 * kc + 1] = kb[kc * 8 + 4];
            }
            float s0[4] = {}, s1[4] = {};
            #pragma unroll
            for (int kc = 0; kc < 4; kc++) {
                mma_tf32(s0, qa[0][kc], kf[2 * kc], kf[2 * kc + 1]);
                mma_tf32(s1, qa[1][kc], kf[2 * kc], kf[2 * kc + 1]);
            }

            float e00 = __expf(s0[0]), e01 = __expf(s0[1]);
            float e02 = __expf(s0[2]), e03 = __expf(s0[3]);
            float e10 = __expf(s1[0]), e11 = __expf(s1[1]);
            float e12 = __expf(s1[2]), e13 = __expf(s1[3]);
            l00 += e00 + e01; l01 += e02 + e03;
            l10 += e10 + e11; l11 += e12 + e13;
            uint32_t pa0[4] = { f2tf32(e00), f2tf32(e02), f2tf32(e01), f2tf32(e03) };
            uint32_t pa1[4] = { f2tf32(e10), f2tf32(e12), f2tf32(e11), f2tf32(e13) };

            uint32_t vf[8];
            const uint32_t* vb0 = (const uint32_t*)(Vs + (nt * 8 + t4) * VSTR + gq);
            const uint32_t* vb1 = vb0 + 4 * VSTR;
            #pragma unroll
            for (int no = 0; no < 4; no++) {
                vf[2 * no]     = vb0[no * 8];
                vf[2 * no + 1] = vb1[no * 8];
            }
            #pragma unroll
            for (int no = 0; no < 4; no++) {
                mma_tf32(o[0][no], pa0, vf[2 * no], vf[2 * no + 1]);
                mma_tf32(o[1][no], pa1, vf[2 * no], vf[2 * no + 1]);
            }
        }
        __syncthreads();
    }

    l00 += __shfl_xor_sync(0xFFFFFFFFu, l00, 1);
    l00 += __shfl_xor_sync(0xFFFFFFFFu, l00, 2);
    l01 += __shfl_xor_sync(0xFFFFFFFFu, l01, 1);
    l01 += __shfl_xor_sync(0xFFFFFFFFu, l01, 2);
    l10 += __shfl_xor_sync(0xFFFFFFFFu, l10, 1);
    l10 += __shfl_xor_sync(0xFFFFFFFFu, l10, 2);
    l11 += __shfl_xor_sync(0xFFFFFFFFu, l11, 1);
    l11 += __shfl_xor_sync(0xFFFFFFFFu, l11, 2);

    const int b = bh >> 3, h = bh & 7;
    #pragma unroll
    for (int mt = 0; mt < 2; mt++) {
        float i0 = 1.f / (mt ? l10 : l00);
        float i1 = 1.f / (mt ? l11 : l01);
        size_t off0 = ((size_t)(b * NT) + n0 + r0 + mt * 16) * CCH + h * DH;
        size_t off8 = off0 + 8 * CCH;
        #pragma unroll
        for (int no = 0; no < 4; no++) {
            int d = no * 8 + 2 * t4;
            float a0 = o[mt][no][0] * i0, a1 = o[mt][no][1] * i0;
            float a2 = o[mt][no][2] * i1, a3 = o[mt][no][3] * i1;
            float h0, l0f, h1, l1f, h2, l2f, h3, l3f;
            tf32_split_f(a0, h0, l0f); tf32_split_f(a1, h1, l1f);
            tf32_split_f(a2, h2, l2f); tf32_split_f(a3, h3, l3f);
            *(float2*)(g_aoh + off0 + d) = make_float2(h0, h1);
            *(float2*)(g_aol + off0 + d) = make_float2(l0f, l1f);
            *(float2*)(g_aoh + off8 + d) = make_float2(h2, h3);
            *(float2*)(g_aol + off8 + d) = make_float2(l2f, l3f);
        }
    }
}

// ---------------------------------------------------------------------------
// Kernel 3: output projection, tf32x3 GEMM, cp.async double-buffered
//   (unchanged from R8 — output needs full precision).
// ---------------------------------------------------------------------------
#define PROJ_STAGE_W 7680

__global__ __launch_bounds__(256, 2) void proj_tc_kernel(
    const float* __restrict__ bias, float* __restrict__ out)
{
    extern __shared__ uint32_t dp[];
    const uint32_t sb = smem_u32(dp);

    const int b  = blockIdx.z;
    const int m0 = blockIdx.x * 128;
    const int o0 = blockIdx.y * 64;
    const int tid  = threadIdx.x;
    const int wid  = tid >> 5;
    const int lane = tid & 31;
    const int gq   = lane >> 2;
    const int t4   = lane & 3;
    const int wm   = wid & 3, wn = wid >> 2;

    const int amm = tid >> 1, akk = (tid & 1) * 8;
    const int boo = tid >> 2, bkk = (tid & 3) * 4;

    const float* ah_g = g_aoh + (size_t)b * NT * CCH;
    const float* al_g = g_aol + (size_t)b * NT * CCH;

    const uint32_t a_off = (uint32_t)(amm * 20 + akk) * 4;
    const uint32_t b_off = (uint32_t)(boo * 20 + bkk) * 4;

    {
        const uint32_t base = sb;
        cp16(base + a_off,                  ah_g + (size_t)(m0 + amm) * CCH + akk);
        cp16(base + a_off + 16,             ah_g + (size_t)(m0 + amm) * CCH + akk + 4);
        cp16(base + 2560 * 4 + a_off,       al_g + (size_t)(m0 + amm) * CCH + akk);
        cp16(base + 2560 * 4 + a_off + 16,  al_g + (size_t)(m0 + amm) * CCH + akk + 4);
        cp16(base + 5120 * 4 + b_off,       g_wph + (size_t)(o0 + boo) * CCH + bkk);
        cp16(base + 6400 * 4 + b_off,       g_wpl + (size_t)(o0 + boo) * CCH + bkk);
    }
    CP_COMMIT();

    float c[2][4][4] = {};

    for (int it = 0; it < 16; it++) {
        if (it + 1 < 16) {
            const int k0 = (it + 1) * 16;
            const uint32_t base = sb + ((it + 1) & 1) * PROJ_STAGE_W * 4;
            cp16(base + a_off,                  ah_g + (size_t)(m0 + amm) * CCH + k0 + akk);
            cp16(base + a_off + 16,             ah_g + (size_t)(m0 + amm) * CCH + k0 + akk + 4);
            cp16(base + 2560 * 4 + a_off,       al_g + (size_t)(m0 + amm) * CCH + k0 + akk);
            cp16(base + 2560 * 4 + a_off + 16,  al_g + (size_t)(m0 + amm) * CCH + k0 + akk + 4);
            cp16(base + 5120 * 4 + b_off,       g_wph + (size_t)(o0 + boo) * CCH + k0 + bkk);
            cp16(base + 6400 * 4 + b_off,       g_wpl + (size_t)(o0 + boo) * CCH + k0 + bkk);
        }
        CP_COMMIT();
        CP_WAIT1();
        __syncthreads();

        const uint32_t* Ah = dp + (it & 1) * PROJ_STAGE_W;
        const uint32_t* Al = Ah + 2560;
        const uint32_t* Bh = Ah + 5120;
        const uint32_t* Bl = Ah + 6400;
        #pragma unroll
        for (int kc = 0; kc < 2; kc++) {
            const int kb = kc * 8;
            uint32_t ah[2][4], al[2][4], bh[4][2], bl[4][2];
            #pragma unroll
            for (int mt = 0; mt < 2; mt++) {
                int m = wm * 32 + mt * 16 + gq;
                ah[mt][0] = Ah[m * 20 + kb + t4];
                al[mt][0] = Al[m * 20 + kb + t4];
                ah[mt][1] = Ah[(m + 8) * 20 + kb + t4];
                al[mt][1] = Al[(m + 8) * 20 + kb + t4];
                ah[mt][2] = Ah[m * 20 + kb + t4 + 4];
                al[mt][2] = Al[m * 20 + kb + t4 + 4];
                ah[mt][3] = Ah[(m + 8) * 20 + kb + t4 + 4];
                al[mt][3] = Al[(m + 8) * 20 + kb + t4 + 4];
            }
            #pragma unroll
            for (int nt = 0; nt < 4; nt++) {
                int n = wn * 32 + nt * 8 + gq;
                bh[nt][0] = Bh[n * 20 + kb + t4];
                bh[nt][1] = Bh[n * 20 + kb + t4 + 4];
                bl[nt][0] = Bl[n * 20 + kb + t4];
                bl[nt][1] = Bl[n * 20 + kb + t4 + 4];
            }
            #pragma unroll
            for (int mt = 0; mt < 2; mt++)
                #pragma unroll
                for (int nt = 0; nt < 4; nt++) {
                    mma_tf32(c[mt][nt], ah[mt], bl[nt][0], bl[nt][1]);
                    mma_tf32(c[mt][nt], al[mt], bh[nt][0], bh[nt][1]);
                    mma_tf32(c[mt][nt], ah[mt], bh[nt][0], bh[nt][1]);
                }
        }
        __syncthreads();
    }

    #pragma unroll
    for (int mt = 0; mt < 2; mt++)
        #pragma unroll
        for (int nt = 0; nt < 4; nt++)
            #pragma unroll
            for (int i = 0; i < 4; i++) {
                int m = m0 + wm * 32 + mt * 16 + gq + ((i >= 2) ? 8 : 0);
                int o = o0 + wn * 32 + nt * 8 + 2 * t4 + (i & 1);
                out[(size_t)b * CCH * NT + (size_t)o * NT + m] =
                    c[mt][nt][i] + __ldg(bias + o);
            }
}

// ---------------------------------------------------------------------------
extern "C" void kernel_launch(void* const* d_in, const int* in_sizes, int n_in,
                              void* d_out, int out_size)
{
    (void)in_sizes; (void)n_in; (void)out_size;
    const float* x      = (const float*)d_in[0];
    const float* w_qkv  = (const float*)d_in[1];
    const float* b_qkv  = (const float*)d_in[2];
    const float* w_proj = (const float*)d_in[3];
    const float* b_proj = (const float*)d_in[4];
    float* out = (float*)d_out;

    cudaFuncSetAttribute(qkv_tc_kernel,
                         cudaFuncAttributeMaxDynamicSharedMemorySize,
                         2 * QKV_STAGE_W * 4);
    cudaFuncSetAttribute(attn_mma_kernel,
                         cudaFuncAttributeMaxDynamicSharedMemorySize, ATT_SMEM);
    cudaFuncSetAttribute(proj_tc_kernel,
                         cudaFuncAttributeMaxDynamicSharedMemorySize,
                         2 * PROJ_STAGE_W * 4);

    split_kernel<<<(XN4 + WQ4 + WP4 + 255) / 256, 256>>>(x, w_qkv, w_proj);

    dim3 g1(NT / 128, O3 / 64, BATCH);
    qkv_tc_kernel<<<g1, 256, 2 * QKV_STAGE_W * 4>>>(b_qkv);

    dim3 g2(NT / MT, BATCH * NH);
    attn_mma_kernel<<<g2, 256, ATT_SMEM>>>();

    dim3 g3(NT / 128, CCH / 64, BATCH);
    proj_tc_kernel<<<g3, 256, 2 * PROJ_STAGE_W * 4>>>(b_proj, out);
}

// round 11
// speedup vs baseline: 1.2810x; 1.0918x over previous
#include <cuda_runtime.h>
#include <cstdint>

// Problem constants
#define BATCH 4
#define CCH   256
#define NH    8
#define DH    32
#define NT    2304
#define O3    768
#define MT    256
#define KT    128
#define NTILE (NT / KT)    // 18

// Scratch (allocation-free rule: __device__ globals)
__device__ float g_q  [BATCH * NH * NT * DH];  // tf32-rounded, scaled by dh^-.5*log2e
__device__ float g_k  [BATCH * NH * NT * DH];  // tf32-rounded
__device__ float g_v  [BATCH * NH * NT * DH];  // tf32-rounded
__device__ float g_ao [BATCH * NT * CCH];      // attention out, tf32-rounded
__device__ float g_xr [BATCH * CCH * NT];      // x, tf32-RNA-rounded
__device__ float g_wqr[O3 * CCH];              // w_qkv, tf32-RNA-rounded
__device__ float g_wpr[CCH * CCH];             // w_proj, tf32-RNA-rounded

__device__ __forceinline__ uint32_t f2tf32(float f) {
    uint32_t r;
    asm("cvt.rna.tf32.f32 %0, %1;" : "=r"(r) : "f"(f));
    return r;
}
__device__ __forceinline__ float ex2f(float x) {
    float r;
    asm("ex2.approx.f32 %0, %1;" : "=f"(r) : "f"(x));
    return r;
}
__device__ __forceinline__ uint32_t smem_u32(const void* p) {
    uint32_t a;
    asm("{ .reg .u64 t; cvta.to.shared.u64 t, %1; cvt.u32.u64 %0, t; }" : "=r"(a) : "l"(p));
    return a;
}
__device__ __forceinline__ void cp16(uint32_t dst, const void* src) {
    asm volatile("cp.async.cg.shared.global [%0], [%1], 16;" :: "r"(dst), "l"(src));
}
#define CP_COMMIT() asm volatile("cp.async.commit_group;" ::: "memory")
#define CP_WAIT1()  asm volatile("cp.async.wait_group 1;" ::: "memory")
#define ONE_TF32 0x3F800000u

__device__ __forceinline__ void mma_tf32(float c[4], const uint32_t a[4],
                                         uint32_t b0, uint32_t b1) {
    asm volatile(
        "mma.sync.aligned.m16n8k8.row.col.f32.tf32.tf32.f32 "
        "{%0,%1,%2,%3}, {%4,%5,%6,%7}, {%8,%9}, {%0,%1,%2,%3};"
        : "+f"(c[0]), "+f"(c[1]), "+f"(c[2]), "+f"(c[3])
        : "r"(a[0]), "r"(a[1]), "r"(a[2]), "r"(a[3]), "r"(b0), "r"(b1));
}

// ---------------------------------------------------------------------------
// Kernel 0: prep — RNA-round x, w_qkv, w_proj to tf32.
// ---------------------------------------------------------------------------
#define XN4 (BATCH * CCH * NT / 4)   // 589824
#define WQ4 (O3 * CCH / 4)           // 49152
#define WP4 (CCH * CCH / 4)          // 16384

__global__ __launch_bounds__(256) void split_kernel(
    const float* __restrict__ x, const float* __restrict__ wq,
    const float* __restrict__ wp)
{
    int i = blockIdx.x * 256 + threadIdx.x;
    const float4* src;
    uint4* dst;
    int j;
    if (i < XN4)                  { src = (const float4*)x;  dst = (uint4*)g_xr;  j = i; }
    else if (i < XN4 + WQ4)       { src = (const float4*)wq; dst = (uint4*)g_wqr; j = i - XN4; }
    else if (i < XN4 + WQ4 + WP4) { src = (const float4*)wp; dst = (uint4*)g_wpr; j = i - XN4 - WQ4; }
    else return;
    float4 f = src[j];
    dst[j] = make_uint4(f2tf32(f.x), f2tf32(f.y), f2tf32(f.z), f2tf32(f.w));
}

// ---------------------------------------------------------------------------
// Kernel 1: QKV projection, single-tf32 GEMM, BK=32, cp.async double-buffered.
//   Stage: A[32][136] ([k][m]) + B[64][36] ([n][k]) = 6656 words.
//   q written pre-scaled by dh^-0.5 * log2(e) (attention uses ex2).
// ---------------------------------------------------------------------------
#define QKV_STAGE_W 6656

__global__ __launch_bounds__(256, 3) void qkv_tc_kernel(const float* __restrict__ bias)
{
    extern __shared__ uint32_t ds[];
    const uint32_t sb = smem_u32(ds);

    const int b  = blockIdx.z;
    const int m0 = blockIdx.x * 128;
    const int o0 = blockIdx.y * 64;
    const int tid  = threadIdx.x;
    const int wid  = tid >> 5;
    const int lane = tid & 31;
    const int gq   = lane >> 2;
    const int t4   = lane & 3;
    const int wm   = wid & 3, wn = wid >> 2;

    const int akk = tid >> 3, amm = (tid & 7) * 16;
    const int boo = tid >> 2, bkk = (tid & 3) * 8;

    const float* xr = g_xr + (size_t)b * CCH * NT;
    const uint32_t a_off = (uint32_t)(akk * 136 + amm) * 4;
    const uint32_t b_off = (uint32_t)(4352 + boo * 36 + bkk) * 4;

    {
        const float* as = xr + (size_t)akk * NT + m0 + amm;
        #pragma unroll
        for (int cv = 0; cv < 4; cv++) cp16(sb + a_off + cv * 16, as + cv * 4);
        const float* bs = g_wqr + (size_t)(o0 + boo) * CCH + bkk;
        cp16(sb + b_off, bs);
        cp16(sb + b_off + 16, bs + 4);
    }
    CP_COMMIT();

    float c[2][4][4] = {};

    for (int it = 0; it < 8; it++) {
        if (it + 1 < 8) {
            const int k0 = (it + 1) * 32;
            const uint32_t base = sb + ((it + 1) & 1) * QKV_STAGE_W * 4;
            const float* as = xr + (size_t)(k0 + akk) * NT + m0 + amm;
            #pragma unroll
            for (int cv = 0; cv < 4; cv++) cp16(base + a_off + cv * 16, as + cv * 4);
            const float* bs = g_wqr + (size_t)(o0 + boo) * CCH + k0 + bkk;
            cp16(base + b_off, bs);
            cp16(base + b_off + 16, bs + 4);
        }
        CP_COMMIT();
        CP_WAIT1();
        __syncthreads();

        const uint32_t* A = ds + (it & 1) * QKV_STAGE_W;
        const uint32_t* B = A + 4352;
        #pragma unroll
        for (int kc = 0; kc < 4; kc++) {
            const int kb = kc * 8;
            uint32_t ah[2][4], bh[4][2];
            #pragma unroll
            for (int mt = 0; mt < 2; mt++) {
                int m = wm * 32 + mt * 16 + gq;
                ah[mt][0] = A[(kb + t4) * 136 + m];
                ah[mt][1] = A[(kb + t4) * 136 + m + 8];
                ah[mt][2] = A[(kb + t4 + 4) * 136 + m];
                ah[mt][3] = A[(kb + t4 + 4) * 136 + m + 8];
            }
            #pragma unroll
            for (int nt = 0; nt < 4; nt++) {
                int n = wn * 32 + nt * 8 + gq;
                bh[nt][0] = B[n * 36 + kb + t4];
                bh[nt][1] = B[n * 36 + kb + t4 + 4];
            }
            #pragma unroll
            for (int mt = 0; mt < 2; mt++)
                #pragma unroll
                for (int nt = 0; nt < 4; nt++)
                    mma_tf32(c[mt][nt], ah[mt], bh[nt][0], bh[nt][1]);
        }
        __syncthreads();
    }

    // epilogue: bias; q scaled by dh^-0.5 * log2(e) for ex2-softmax
    const float scale = 0.25503487f;
    #pragma unroll
    for (int mt = 0; mt < 2; mt++)
        #pragma unroll
        for (int nt = 0; nt < 4; nt++)
            #pragma unroll
            for (int i = 0; i < 4; i++) {
                int m = m0 + wm * 32 + mt * 16 + gq + ((i >= 2) ? 8 : 0);
                int o = o0 + wn * 32 + nt * 8 + 2 * t4 + (i & 1);
                float val = c[mt][nt][i] + __ldg(bias + o);
                int kind = o / CCH;
                int oc = o % CCH;
                int h = oc / DH, d = oc % DH;
                int idx = ((b * NH + h) * NT + m) * DH + d;
                if (kind == 0)
                    g_q[idx] = __uint_as_float(f2tf32(val * scale));
                else if (kind == 1)
                    g_k[idx] = __uint_as_float(f2tf32(val));
                else
                    g_v[idx] = __uint_as_float(f2tf32(val));
            }
}

// ---------------------------------------------------------------------------
// Kernel 2: tf32 flash attention, MT=256, cp.async double-buffered.
//   exp via bare ex2 (log2e folded into q); row-sum l via ones-MMA
//   (2 extra HMMAs/nt replace 8 FADDs + epilogue shuffles).
// ---------------------------------------------------------------------------
#define KSTR 36
#define VSTR 40
#define ATT_STAGE_W (KT * KSTR + KT * VSTR)
#define ATT_SMEM    (2 * ATT_STAGE_W * 4)

__global__ __launch_bounds__(256, 2) void attn_mma_kernel()
{
    extern __shared__ float smf[];
    const uint32_t smbase = smem_u32(smf);

    const int bh   = blockIdx.y;
    const int n0   = blockIdx.x * MT;
    const int tid  = threadIdx.x;
    const int wid  = tid >> 5;
    const int lane = tid & 31;
    const int gq   = lane >> 2;
    const int t4   = lane & 3;
    const int r0   = wid * 32 + gq;

    const int srow = tid >> 1;
    const int half = tid & 1;
    const int si   = srow & 7;
    const int prow = (srow & ~7) | ((si & 3) * 2) | (si >> 2);
    const float* kbase = g_k + ((size_t)bh * NT + srow) * DH + half * 16;
    const float* vbase = g_v + ((size_t)bh * NT + srow) * DH + half * 16;

    uint32_t qa[2][4][4];
    #pragma unroll
    for (int mt = 0; mt < 2; mt++) {
        const float* Q0 = g_q + ((size_t)bh * NT + n0 + r0 + mt * 16) * DH;
        const float* Q8 = Q0 + 8 * DH;
        #pragma unroll
        for (int kc = 0; kc < 4; kc++) {
            qa[mt][kc][0] = __float_as_uint(Q0[kc * 8 + t4]);
            qa[mt][kc][1] = __float_as_uint(Q8[kc * 8 + t4]);
            qa[mt][kc][2] = __float_as_uint(Q0[kc * 8 + t4 + 4]);
            qa[mt][kc][3] = __float_as_uint(Q8[kc * 8 + t4 + 4]);
        }
    }

    float o[2][4][4] = {};
    float la[2][4] = {};   // row-sum accumulators via ones-MMA

    {
        uint32_t kdst = smbase + (prow * KSTR + half * 16) * 4;
        uint32_t vdst = smbase + (KT * KSTR + srow * VSTR + half * 16) * 4;
        #pragma unroll
        for (int cv = 0; cv < 4; cv++) {
            cp16(kdst + cv * 16, kbase + cv * 4);
            cp16(vdst + cv * 16, vbase + cv * 4);
        }
    }
    CP_COMMIT();

    for (int t = 0; t < NTILE; t++) {
        if (t + 1 < NTILE) {
            const int bs = (t + 1) & 1;
            uint32_t kdst = smbase + (bs * ATT_STAGE_W + prow * KSTR + half * 16) * 4;
            uint32_t vdst = smbase + (bs * ATT_STAGE_W + KT * KSTR + srow * VSTR + half * 16) * 4;
            const float* ks = kbase + (size_t)(t + 1) * KT * DH;
            const float* vs = vbase + (size_t)(t + 1) * KT * DH;
            #pragma unroll
            for (int cv = 0; cv < 4; cv++) {
                cp16(kdst + cv * 16, ks + cv * 4);
                cp16(vdst + cv * 16, vs + cv * 4);
            }
        }
        CP_COMMIT();
        CP_WAIT1();
        __syncthreads();

        const float* Ks = smf + (t & 1) * ATT_STAGE_W;
        const float* Vs = Ks + KT * KSTR;

        #pragma unroll 2
        for (int nt = 0; nt < 16; nt++) {
            uint32_t kf[8];
            const uint32_t* kb = (const uint32_t*)(Ks + (nt * 8 + gq) * KSTR + t4);
            #pragma unroll
            for (int kc = 0; kc < 4; kc++) {
                kf[2 * kc]     = kb[kc * 8];
                kf[2 * kc + 1] = kb[kc * 8 + 4];
            }
            float s0[4] = {}, s1[4] = {};
            #pragma unroll
            for (int kc = 0; kc < 4; kc++) {
                mma_tf32(s0, qa[0][kc], kf[2 * kc], kf[2 * kc + 1]);
                mma_tf32(s1, qa[1][kc], kf[2 * kc], kf[2 * kc + 1]);
            }

            float e00 = ex2f(s0[0]), e01 = ex2f(s0[1]);
            float e02 = ex2f(s0[2]), e03 = ex2f(s0[3]);
            float e10 = ex2f(s1[0]), e11 = ex2f(s1[1]);
            float e12 = ex2f(s1[2]), e13 = ex2f(s1[3]);
            uint32_t pa0[4] = { f2tf32(e00), f2tf32(e02), f2tf32(e01), f2tf32(e03) };
            uint32_t pa1[4] = { f2tf32(e10), f2tf32(e12), f2tf32(e11), f2tf32(e13) };

            // row sums via ones-MMA (every output column = P row-sum)
            mma_tf32(la[0], pa0, ONE_TF32, ONE_TF32);
            mma_tf32(la[1], pa1, ONE_TF32, ONE_TF32);

            uint32_t vf[8];
            const uint32_t* vb0 = (const uint32_t*)(Vs + (nt * 8 + t4) * VSTR + gq);
            const uint32_t* vb1 = vb0 + 4 * VSTR;
            #pragma unroll
            for (int no = 0; no < 4; no++) {
                vf[2 * no]     = vb0[no * 8];
                vf[2 * no + 1] = vb1[no * 8];
            }
            #pragma unroll
            for (int no = 0; no < 4; no++) {
                mma_tf32(o[0][no], pa0, vf[2 * no], vf[2 * no + 1]);
                mma_tf32(o[1][no], pa1, vf[2 * no], vf[2 * no + 1]);
            }
        }
        __syncthreads();
    }

    // finalize: normalize by MMA row sums (c0 = row r, c2 = row r+8), write
    // g_ao tf32-rounded so proj can run single-pass on rounded inputs.
    const int b = bh >> 3, h = bh & 7;
    #pragma unroll
    for (int mt = 0; mt < 2; mt++) {
        float i0 = 1.f / la[mt][0];
        float i1 = 1.f / la[mt][2];
        size_t off0 = ((size_t)(b * NT) + n0 + r0 + mt * 16) * CCH + h * DH;
        size_t off8 = off0 + 8 * CCH;
        #pragma unroll
        for (int no = 0; no < 4; no++) {
            int d = no * 8 + 2 * t4;
            uint32_t r00 = f2tf32(o[mt][no][0] * i0);
            uint32_t r01 = f2tf32(o[mt][no][1] * i0);
            uint32_t r10 = f2tf32(o[mt][no][2] * i1);
            uint32_t r11 = f2tf32(o[mt][no][3] * i1);
            *(float2*)(g_ao + off0 + d) =
                make_float2(__uint_as_float(r00), __uint_as_float(r01));
            *(float2*)(g_ao + off8 + d) =
                make_float2(__uint_as_float(r10), __uint_as_float(r11));
        }
    }
}

// ---------------------------------------------------------------------------
// Kernel 3: output projection, single-tf32 GEMM, BK=32, cp.async
//   double-buffered (inputs pre-rounded: g_ao by attention, g_wpr by split).
//   Stage: A[128][36] ([m][k]) + B[64][36] ([n][k]) = 6912 words.
// ---------------------------------------------------------------------------
#define PROJ_STAGE_W 6912

__global__ __launch_bounds__(256, 3) void proj_tc_kernel(
    const float* __restrict__ bias, float* __restrict__ out)
{
    extern __shared__ uint32_t dp[];
    const uint32_t sb = smem_u32(dp);

    const int b  = blockIdx.z;
    const int m0 = blockIdx.x * 128;
    const int o0 = blockIdx.y * 64;
    const int tid  = threadIdx.x;
    const int wid  = tid >> 5;
    const int lane = tid & 31;
    const int gq   = lane >> 2;
    const int t4   = lane & 3;
    const int wm   = wid & 3, wn = wid >> 2;

    const int amm = tid >> 1, akk = (tid & 1) * 16;
    const int boo = tid >> 2, bkk = (tid & 3) * 8;

    const float* ag = g_ao + (size_t)b * NT * CCH;
    const uint32_t a_off = (uint32_t)(amm * 36 + akk) * 4;
    const uint32_t b_off = (uint32_t)(4608 + boo * 36 + bkk) * 4;

    {
        const float* as = ag + (size_t)(m0 + amm) * CCH + akk;
        #pragma unroll
        for (int cv = 0; cv < 4; cv++) cp16(sb + a_off + cv * 16, as + cv * 4);
        const float* bs = g_wpr + (size_t)(o0 + boo) * CCH + bkk;
        cp16(sb + b_off, bs);
        cp16(sb + b_off + 16, bs + 4);
    }
    CP_COMMIT();

    float c[2][4][4] = {};

    for (int it = 0; it < 8; it++) {
        if (it + 1 < 8) {
            const int k0 = (it + 1) * 32;
            const uint32_t base = sb + ((it + 1) & 1) * PROJ_STAGE_W * 4;
            const float* as = ag + (size_t)(m0 + amm) * CCH + k0 + akk;
            #pragma unroll
            for (int cv = 0; cv < 4; cv++) cp16(base + a_off + cv * 16, as + cv * 4);
            const float* bs = g_wpr + (size_t)(o0 + boo) * CCH + k0 + bkk;
            cp16(base + b_off, bs);
            cp16(base + b_off + 16, bs + 4);
        }
        CP_COMMIT();
        CP_WAIT1();
        __syncthreads();

        const uint32_t* A = dp + (it & 1) * PROJ_STAGE_W;
        const uint32_t* B = A + 4608;
        #pragma unroll
        for (int kc = 0; kc < 4; kc++) {
            const int kb = kc * 8;
            uint32_t ah[2][4], bh[4][2];
            #pragma unroll
            for (int mt = 0; mt < 2; mt++) {
                int m = wm * 32 + mt * 16 + gq;
                ah[mt][0] = A[m * 36 + kb + t4];
                ah[mt][1] = A[(m + 8) * 36 + kb + t4];
                ah[mt][2] = A[m * 36 + kb + t4 + 4];
                ah[mt][3] = A[(m + 8) * 36 + kb + t4 + 4];
            }
            #pragma unroll
            for (int nt = 0; nt < 4; nt++) {
                int n = wn * 32 + nt * 8 + gq;
                bh[nt][0] = B[n * 36 + kb + t4];
                bh[nt][1] = B[n * 36 + kb + t4 + 4];
            }
            #pragma unroll
            for (int mt = 0; mt < 2; mt++)
                #pragma unroll
                for (int nt = 0; nt < 4; nt++)
                    mma_tf32(c[mt][nt], ah[mt], bh[nt][0], bh[nt][1]);
        }
        __syncthreads();
    }

    #pragma unroll
    for (int mt = 0; mt < 2; mt++)
        #pragma unroll
        for (int nt = 0; nt < 4; nt++)
            #pragma unroll
            for (int i = 0; i < 4; i++) {
                int m = m0 + wm * 32 + mt * 16 + gq + ((i >= 2) ? 8 : 0);
                int o = o0 + wn * 32 + nt * 8 + 2 * t4 + (i & 1);
                out[(size_t)b * CCH * NT + (size_t)o * NT + m] =
                    c[mt][nt][i] + __ldg(bias + o);
            }
}

// ---------------------------------------------------------------------------
extern "C" void kernel_launch(void* const* d_in, const int* in_sizes, int n_in,
                              void* d_out, int out_size)
{
    (void)in_sizes; (void)n_in; (void)out_size;
    const float* x      = (const float*)d_in[0];
    const float* w_qkv  = (const float*)d_in[1];
    const float* b_qkv  = (const float*)d_in[2];
    const float* w_proj = (const float*)d_in[3];
    const float* b_proj = (const float*)d_in[4];
    float* out = (float*)d_out;

    cudaFuncSetAttribute(qkv_tc_kernel,
                         cudaFuncAttributeMaxDynamicSharedMemorySize,
                         2 * QKV_STAGE_W * 4);
    cudaFuncSetAttribute(attn_mma_kernel,
                         cudaFuncAttributeMaxDynamicSharedMemorySize, ATT_SMEM);
    cudaFuncSetAttribute(proj_tc_kernel,
                         cudaFuncAttributeMaxDynamicSharedMemorySize,
                         2 * PROJ_STAGE_W * 4);

    split_kernel<<<(XN4 + WQ4 + WP4 + 255) / 256, 256>>>(x, w_qkv, w_proj);

    dim3 g1(NT / 128, O3 / 64, BATCH);
    qkv_tc_kernel<<<g1, 256, 2 * QKV_STAGE_W * 4>>>(b_qkv);

    dim3 g2(NT / MT, BATCH * NH);
    attn_mma_kernel<<<g2, 256, ATT_SMEM>>>();

    dim3 g3(NT / 128, CCH / 64, BATCH);
    proj_tc_kernel<<<g3, 256, 2 * PROJ_STAGE_W * 4>>>(b_proj, out);
}

// round 12
// speedup vs baseline: 1.8952x; 1.4794x over previous
#include <cuda_runtime.h>
#include <cuda_fp16.h>
#include <cstdint>

// Problem constants
#define BATCH 4
#define CCH   256
#define NH    8
#define DH    32
#define NT    2304
#define O3    768
#define MT    256
#define KT    128
#define NTILE (NT / KT)    // 18

// Scratch (allocation-free rule: __device__ globals)
__device__ __half g_qh[BATCH * NH * NT * DH];  // fp16, scaled by dh^-.5*log2e
__device__ __half g_kh[BATCH * NH * NT * DH];  // fp16
__device__ __half g_vh[BATCH * NH * NT * DH];  // fp16
__device__ float  g_ao [BATCH * NT * CCH];     // attention out, tf32-rounded
__device__ float  g_xr [BATCH * CCH * NT];     // x, tf32-RNA-rounded
__device__ float  g_wqr[O3 * CCH];             // w_qkv, tf32-RNA-rounded
__device__ float  g_wpr[CCH * CCH];            // w_proj, tf32-RNA-rounded

__device__ __forceinline__ uint32_t f2tf32(float f) {
    uint32_t r;
    asm("cvt.rna.tf32.f32 %0, %1;" : "=r"(r) : "f"(f));
    return r;
}
__device__ __forceinline__ float ex2f(float x) {
    float r;
    asm("ex2.approx.f32 %0, %1;" : "=f"(r) : "f"(x));
    return r;
}
__device__ __forceinline__ uint32_t pack_h2(float lo, float hi) {
    uint32_t r;
    asm("cvt.rn.f16x2.f32 %0, %1, %2;" : "=r"(r) : "f"(hi), "f"(lo));
    return r;
}
__device__ __forceinline__ uint32_t smem_u32(const void* p) {
    uint32_t a;
    asm("{ .reg .u64 t; cvta.to.shared.u64 t, %1; cvt.u32.u64 %0, t; }" : "=r"(a) : "l"(p));
    return a;
}
__device__ __forceinline__ void cp16(uint32_t dst, const void* src) {
    asm volatile("cp.async.cg.shared.global [%0], [%1], 16;" :: "r"(dst), "l"(src));
}
#define CP_COMMIT() asm volatile("cp.async.commit_group;" ::: "memory")
#define CP_WAIT1()  asm volatile("cp.async.wait_group 1;" ::: "memory")
#define ONE_H2 0x3C003C00u

__device__ __forceinline__ void mma_tf32(float c[4], const uint32_t a[4],
                                         uint32_t b0, uint32_t b1) {
    asm volatile(
        "mma.sync.aligned.m16n8k8.row.col.f32.tf32.tf32.f32 "
        "{%0,%1,%2,%3}, {%4,%5,%6,%7}, {%8,%9}, {%0,%1,%2,%3};"
        : "+f"(c[0]), "+f"(c[1]), "+f"(c[2]), "+f"(c[3])
        : "r"(a[0]), "r"(a[1]), "r"(a[2]), "r"(a[3]), "r"(b0), "r"(b1));
}
__device__ __forceinline__ void mma_f16(float c[4], const uint32_t a[4],
                                        uint32_t b0, uint32_t b1) {
    asm volatile(
        "mma.sync.aligned.m16n8k16.row.col.f32.f16.f16.f32 "
        "{%0,%1,%2,%3}, {%4,%5,%6,%7}, {%8,%9}, {%0,%1,%2,%3};"
        : "+f"(c[0]), "+f"(c[1]), "+f"(c[2]), "+f"(c[3])
        : "r"(a[0]), "r"(a[1]), "r"(a[2]), "r"(a[3]), "r"(b0), "r"(b1));
}
__device__ __forceinline__ void ldsm4t(uint32_t& r0, uint32_t& r1,
                                       uint32_t& r2, uint32_t& r3, uint32_t addr) {
    asm volatile(
        "ldmatrix.sync.aligned.m8n8.x4.trans.shared.b16 {%0,%1,%2,%3}, [%4];"
        : "=r"(r0), "=r"(r1), "=r"(r2), "=r"(r3) : "r"(addr));
}

// ---------------------------------------------------------------------------
// Kernel 0: prep — RNA-round x, w_qkv, w_proj to tf32.  (unchanged)
// ---------------------------------------------------------------------------
#define XN4 (BATCH * CCH * NT / 4)
#define WQ4 (O3 * CCH / 4)
#define WP4 (CCH * CCH / 4)

__global__ __launch_bounds__(256) void split_kernel(
    const float* __restrict__ x, const float* __restrict__ wq,
    const float* __restrict__ wp)
{
    int i = blockIdx.x * 256 + threadIdx.x;
    const float4* src;
    uint4* dst;
    int j;
    if (i < XN4)                  { src = (const float4*)x;  dst = (uint4*)g_xr;  j = i; }
    else if (i < XN4 + WQ4)       { src = (const float4*)wq; dst = (uint4*)g_wqr; j = i - XN4; }
    else if (i < XN4 + WQ4 + WP4) { src = (const float4*)wp; dst = (uint4*)g_wpr; j = i - XN4 - WQ4; }
    else return;
    float4 f = src[j];
    dst[j] = make_uint4(f2tf32(f.x), f2tf32(f.y), f2tf32(f.z), f2tf32(f.w));
}

// ---------------------------------------------------------------------------
// Kernel 1: QKV projection, single-tf32 GEMM, BK=32 (unchanged loop).
//   Epilogue now writes fp16 q/k/v (same 10-bit mantissa as tf32 rounding).
// ---------------------------------------------------------------------------
#define QKV_STAGE_W 6656

__global__ __launch_bounds__(256, 3) void qkv_tc_kernel(const float* __restrict__ bias)
{
    extern __shared__ uint32_t ds[];
    const uint32_t sb = smem_u32(ds);

    const int b  = blockIdx.z;
    const int m0 = blockIdx.x * 128;
    const int o0 = blockIdx.y * 64;
    const int tid  = threadIdx.x;
    const int wid  = tid >> 5;
    const int lane = tid & 31;
    const int gq   = lane >> 2;
    const int t4   = lane & 3;
    const int wm   = wid & 3, wn = wid >> 2;

    const int akk = tid >> 3, amm = (tid & 7) * 16;
    const int boo = tid >> 2, bkk = (tid & 3) * 8;

    const float* xr = g_xr + (size_t)b * CCH * NT;
    const uint32_t a_off = (uint32_t)(akk * 136 + amm) * 4;
    const uint32_t b_off = (uint32_t)(4352 + boo * 36 + bkk) * 4;

    {
        const float* as = xr + (size_t)akk * NT + m0 + amm;
        #pragma unroll
        for (int cv = 0; cv < 4; cv++) cp16(sb + a_off + cv * 16, as + cv * 4);
        const float* bs = g_wqr + (size_t)(o0 + boo) * CCH + bkk;
        cp16(sb + b_off, bs);
        cp16(sb + b_off + 16, bs + 4);
    }
    CP_COMMIT();

    float c[2][4][4] = {};

    for (int it = 0; it < 8; it++) {
        if (it + 1 < 8) {
            const int k0 = (it + 1) * 32;
            const uint32_t base = sb + ((it + 1) & 1) * QKV_STAGE_W * 4;
            const float* as = xr + (size_t)(k0 + akk) * NT + m0 + amm;
            #pragma unroll
            for (int cv = 0; cv < 4; cv++) cp16(base + a_off + cv * 16, as + cv * 4);
            const float* bs = g_wqr + (size_t)(o0 + boo) * CCH + k0 + bkk;
            cp16(base + b_off, bs);
            cp16(base + b_off + 16, bs + 4);
        }
        CP_COMMIT();
        CP_WAIT1();
        __syncthreads();

        const uint32_t* A = ds + (it & 1) * QKV_STAGE_W;
        const uint32_t* B = A + 4352;
        #pragma unroll
        for (int kc = 0; kc < 4; kc++) {
            const int kb = kc * 8;
            uint32_t ah[2][4], bh[4][2];
            #pragma unroll
            for (int mt = 0; mt < 2; mt++) {
                int m = wm * 32 + mt * 16 + gq;
                ah[mt][0] = A[(kb + t4) * 136 + m];
                ah[mt][1] = A[(kb + t4) * 136 + m + 8];
                ah[mt][2] = A[(kb + t4 + 4) * 136 + m];
                ah[mt][3] = A[(kb + t4 + 4) * 136 + m + 8];
            }
            #pragma unroll
            for (int nt = 0; nt < 4; nt++) {
                int n = wn * 32 + nt * 8 + gq;
                bh[nt][0] = B[n * 36 + kb + t4];
                bh[nt][1] = B[n * 36 + kb + t4 + 4];
            }
            #pragma unroll
            for (int mt = 0; mt < 2; mt++)
                #pragma unroll
                for (int nt = 0; nt < 4; nt++)
                    mma_tf32(c[mt][nt], ah[mt], bh[nt][0], bh[nt][1]);
        }
        __syncthreads();
    }

    // epilogue: bias; q scaled by dh^-0.5 * log2(e); fp16 outputs
    const float scale = 0.25503487f;
    #pragma unroll
    for (int mt = 0; mt < 2; mt++)
        #pragma unroll
        for (int nt = 0; nt < 4; nt++)
            #pragma unroll
            for (int i = 0; i < 4; i++) {
                int m = m0 + wm * 32 + mt * 16 + gq + ((i >= 2) ? 8 : 0);
                int o = o0 + wn * 32 + nt * 8 + 2 * t4 + (i & 1);
                float val = c[mt][nt][i] + __ldg(bias + o);
                int kind = o / CCH;
                int oc = o % CCH;
                int h = oc / DH, d = oc % DH;
                int idx = ((b * NH + h) * NT + m) * DH + d;
                if (kind == 0)
                    g_qh[idx] = __float2half_rn(val * scale);
                else if (kind == 1)
                    g_kh[idx] = __float2half_rn(val);
                else
                    g_vh[idx] = __float2half_rn(val);
            }
}

// ---------------------------------------------------------------------------
// Kernel 2: fp16 m16n8k16 flash attention, MT=256, cp.async double-buffered.
//   Per 16-key chunk: S via 2 k16 MMAs/group/mt; P C-frags map directly to
//   A-frags (no permutation); V B-frags via ldmatrix.x4.trans; row sums via
//   ones-MMA. KSTR_H=40 halves (80 B rows, conflict-free, 16B-aligned).
// ---------------------------------------------------------------------------
#define KSTR_H 40
#define STAGE_HALVES (2 * KT * KSTR_H)        // K + V in halves = 10240
#define ATT_STAGE_B  (STAGE_HALVES * 2)       // 20480 bytes
#define ATT_SMEM     (2 * ATT_STAGE_B)        // 40960 bytes

__global__ __launch_bounds__(256, 2) void attn_mma_kernel()
{
    extern __shared__ __half smh[];
    const uint32_t smbase = smem_u32(smh);

    const int bh   = blockIdx.y;
    const int n0   = blockIdx.x * MT;
    const int tid  = threadIdx.x;
    const int wid  = tid >> 5;
    const int lane = tid & 31;
    const int gq   = lane >> 2;
    const int t4   = lane & 3;
    const int r0   = wid * 32 + gq;

    // staging coords: 2 threads per key row, 32-byte halves
    const int srow = tid >> 1;
    const int shalf = tid & 1;
    const __half* kbase = g_kh + ((size_t)bh * NT + srow) * DH + shalf * 16;
    const __half* vbase = g_vh + ((size_t)bh * NT + srow) * DH + shalf * 16;
    const uint32_t kdst_off = (uint32_t)(srow * KSTR_H + shalf * 16) * 2;
    const uint32_t vdst_off = kdst_off + KT * KSTR_H * 2;

    // ldmatrix address pieces (V): row = c*16 + (lane&15), halfoff = (lane>>4)*8
    const uint32_t lrow = lane & 15;
    const uint32_t lhof = (lane >> 4) * 8;

    // Q fragments: [mt][kc][4]
    uint32_t qa[2][2][4];
    #pragma unroll
    for (int mt = 0; mt < 2; mt++) {
        const __half* Q0 = g_qh + ((size_t)bh * NT + n0 + r0 + mt * 16) * DH;
        const __half* Q8 = Q0 + 8 * DH;
        #pragma unroll
        for (int kc = 0; kc < 2; kc++) {
            qa[mt][kc][0] = *(const uint32_t*)(Q0 + 2 * t4 + 16 * kc);
            qa[mt][kc][1] = *(const uint32_t*)(Q8 + 2 * t4 + 16 * kc);
            qa[mt][kc][2] = *(const uint32_t*)(Q0 + 2 * t4 + 8 + 16 * kc);
            qa[mt][kc][3] = *(const uint32_t*)(Q8 + 2 * t4 + 8 + 16 * kc);
        }
    }

    float o[2][4][4] = {};   // [mt][db][frag]
    float la[2][4] = {};     // row sums via ones-MMA

    // prologue: stage tile 0
    {
        #pragma unroll
        for (int cv = 0; cv < 2; cv++) {
            cp16(smbase + kdst_off + cv * 16, kbase + cv * 8);
            cp16(smbase + vdst_off + cv * 16, vbase + cv * 8);
        }
    }
    CP_COMMIT();

    for (int t = 0; t < NTILE; t++) {
        if (t + 1 < NTILE) {
            const uint32_t base = smbase + ((t + 1) & 1) * ATT_STAGE_B;
            const __half* ks = kbase + (size_t)(t + 1) * KT * DH;
            const __half* vs = vbase + (size_t)(t + 1) * KT * DH;
            #pragma unroll
            for (int cv = 0; cv < 2; cv++) {
                cp16(base + kdst_off + cv * 16, ks + cv * 8);
                cp16(base + vdst_off + cv * 16, vs + cv * 8);
            }
        }
        CP_COMMIT();
        CP_WAIT1();
        __syncthreads();

        const __half* Ksp = smh + (t & 1) * STAGE_HALVES;
        const uint32_t vsm = smbase + (t & 1) * ATT_STAGE_B + KT * KSTR_H * 2;

        #pragma unroll 2
        for (int c = 0; c < 8; c++) {
            // ---- K fragments: [g][kc][b]
            uint32_t kb[2][2][2];
            #pragma unroll
            for (int g = 0; g < 2; g++) {
                const __half* kr = Ksp + (c * 16 + 8 * g + gq) * KSTR_H + 2 * t4;
                #pragma unroll
                for (int kc = 0; kc < 2; kc++) {
                    kb[g][kc][0] = *(const uint32_t*)(kr + 16 * kc);
                    kb[g][kc][1] = *(const uint32_t*)(kr + 16 * kc + 8);
                }
            }
            // ---- S = Q K^T
            float s[2][2][4] = {};   // [g][mt]
            #pragma unroll
            for (int g = 0; g < 2; g++)
                #pragma unroll
                for (int mt = 0; mt < 2; mt++) {
                    mma_f16(s[g][mt], qa[mt][0], kb[g][0][0], kb[g][0][1]);
                    mma_f16(s[g][mt], qa[mt][1], kb[g][1][0], kb[g][1][1]);
                }
            // ---- P = exp2(S), packed directly into A-fragments
            uint32_t pa[2][4];
            #pragma unroll
            for (int mt = 0; mt < 2; mt++) {
                pa[mt][0] = pack_h2(ex2f(s[0][mt][0]), ex2f(s[0][mt][1]));
                pa[mt][1] = pack_h2(ex2f(s[0][mt][2]), ex2f(s[0][mt][3]));
                pa[mt][2] = pack_h2(ex2f(s[1][mt][0]), ex2f(s[1][mt][1]));
                pa[mt][3] = pack_h2(ex2f(s[1][mt][2]), ex2f(s[1][mt][3]));
            }
            // ---- row sums via ones-MMA
            mma_f16(la[0], pa[0], ONE_H2, ONE_H2);
            mma_f16(la[1], pa[1], ONE_H2, ONE_H2);
            // ---- V fragments via ldmatrix.x4.trans: [db][b]
            uint32_t vb[4][2];
            uint32_t va = vsm + ((c * 16 + lrow) * KSTR_H + lhof) * 2;
            ldsm4t(vb[0][0], vb[0][1], vb[1][0], vb[1][1], va);
            ldsm4t(vb[2][0], vb[2][1], vb[3][0], vb[3][1], va + 32);
            // ---- O += P V
            #pragma unroll
            for (int mt = 0; mt < 2; mt++)
                #pragma unroll
                for (int db = 0; db < 4; db++)
                    mma_f16(o[mt][db], pa[mt], vb[db][0], vb[db][1]);
        }
        __syncthreads();
    }

    // finalize: normalize by MMA row sums; write g_ao tf32-rounded for proj
    const int b = bh >> 3, h = bh & 7;
    #pragma unroll
    for (int mt = 0; mt < 2; mt++) {
        float i0 = 1.f / la[mt][0];
        float i1 = 1.f / la[mt][2];
        size_t off0 = ((size_t)(b * NT) + n0 + r0 + mt * 16) * CCH + h * DH;
        size_t off8 = off0 + 8 * CCH;
        #pragma unroll
        for (int db = 0; db < 4; db++) {
            int d = db * 8 + 2 * t4;
            uint32_t r00 = f2tf32(o[mt][db][0] * i0);
            uint32_t r01 = f2tf32(o[mt][db][1] * i0);
            uint32_t r10 = f2tf32(o[mt][db][2] * i1);
            uint32_t r11 = f2tf32(o[mt][db][3] * i1);
            *(float2*)(g_ao + off0 + d) =
                make_float2(__uint_as_float(r00), __uint_as_float(r01));
            *(float2*)(g_ao + off8 + d) =
                make_float2(__uint_as_float(r10), __uint_as_float(r11));
        }
    }
}

// ---------------------------------------------------------------------------
// Kernel 3: output projection, single-tf32 GEMM, BK=32 (unchanged).
// ---------------------------------------------------------------------------
#define PROJ_STAGE_W 6912

__global__ __launch_bounds__(256, 3) void proj_tc_kernel(
    const float* __restrict__ bias, float* __restrict__ out)
{
    extern __shared__ uint32_t dp[];
    const uint32_t sb = smem_u32(dp);

    const int b  = blockIdx.z;
    const int m0 = blockIdx.x * 128;
    const int o0 = blockIdx.y * 64;
    const int tid  = threadIdx.x;
    const int wid  = tid >> 5;
    const int lane = tid & 31;
    const int gq   = lane >> 2;
    const int t4   = lane & 3;
    const int wm   = wid & 3, wn = wid >> 2;

    const int amm = tid >> 1, akk = (tid & 1) * 16;
    const int boo = tid >> 2, bkk = (tid & 3) * 8;

    const float* ag = g_ao + (size_t)b * NT * CCH;
    const uint32_t a_off = (uint32_t)(amm * 36 + akk) * 4;
    const uint32_t b_off = (uint32_t)(4608 + boo * 36 + bkk) * 4;

    {
        const float* as = ag + (size_t)(m0 + amm) * CCH + akk;
        #pragma unroll
        for (int cv = 0; cv < 4; cv++) cp16(sb + a_off + cv * 16, as + cv * 4);
        const float* bs = g_wpr + (size_t)(o0 + boo) * CCH + bkk;
        cp16(sb + b_off, bs);
        cp16(sb + b_off + 16, bs + 4);
    }
    CP_COMMIT();

    float c[2][4][4] = {};

    for (int it = 0; it < 8; it++) {
        if (it + 1 < 8) {
            const int k0 = (it + 1) * 32;
            const uint32_t base = sb + ((it + 1) & 1) * PROJ_STAGE_W * 4;
            const float* as = ag + (size_t)(m0 + amm) * CCH + k0 + akk;
            #pragma unroll
            for (int cv = 0; cv < 4; cv++) cp16(base + a_off + cv * 16, as + cv * 4);
            const float* bs = g_wpr + (size_t)(o0 + boo) * CCH + k0 + bkk;
            cp16(base + b_off, bs);
            cp16(base + b_off + 16, bs + 4);
        }
        CP_COMMIT();
        CP_WAIT1();
        __syncthreads();

        const uint32_t* A = dp + (it & 1) * PROJ_STAGE_W;
        const uint32_t* B = A + 4608;
        #pragma unroll
        for (int kc = 0; kc < 4; kc++) {
            const int kb = kc * 8;
            uint32_t ah[2][4], bh[4][2];
            #pragma unroll
            for (int mt = 0; mt < 2; mt++) {
                int m = wm * 32 + mt * 16 + gq;
                ah[mt][0] = A[m * 36 + kb + t4];
                ah[mt][1] = A[(m + 8) * 36 + kb + t4];
                ah[mt][2] = A[m * 36 + kb + t4 + 4];
                ah[mt][3] = A[(m + 8) * 36 + kb + t4 + 4];
            }
            #pragma unroll
            for (int nt = 0; nt < 4; nt++) {
                int n = wn * 32 + nt * 8 + gq;
                bh[nt][0] = B[n * 36 + kb + t4];
                bh[nt][1] = B[n * 36 + kb + t4 + 4];
            }
            #pragma unroll
            for (int mt = 0; mt < 2; mt++)
                #pragma unroll
                for (int nt = 0; nt < 4; nt++)
                    mma_tf32(c[mt][nt], ah[mt], bh[nt][0], bh[nt][1]);
        }
        __syncthreads();
    }

    #pragma unroll
    for (int mt = 0; mt < 2; mt++)
        #pragma unroll
        for (int nt = 0; nt < 4; nt++)
            #pragma unroll
            for (int i = 0; i < 4; i++) {
                int m = m0 + wm * 32 + mt * 16 + gq + ((i >= 2) ? 8 : 0);
                int o = o0 + wn * 32 + nt * 8 + 2 * t4 + (i & 1);
                out[(size_t)b * CCH * NT + (size_t)o * NT + m] =
                    c[mt][nt][i] + __ldg(bias + o);
            }
}

// ---------------------------------------------------------------------------
extern "C" void kernel_launch(void* const* d_in, const int* in_sizes, int n_in,
                              void* d_out, int out_size)
{
    (void)in_sizes; (void)n_in; (void)out_size;
    const float* x      = (const float*)d_in[0];
    const float* w_qkv  = (const float*)d_in[1];
    const float* b_qkv  = (const float*)d_in[2];
    const float* w_proj = (const float*)d_in[3];
    const float* b_proj = (const float*)d_in[4];
    float* out = (float*)d_out;

    cudaFuncSetAttribute(qkv_tc_kernel,
                         cudaFuncAttributeMaxDynamicSharedMemorySize,
                         2 * QKV_STAGE_W * 4);
    cudaFuncSetAttribute(attn_mma_kernel,
                         cudaFuncAttributeMaxDynamicSharedMemorySize, ATT_SMEM);
    cudaFuncSetAttribute(proj_tc_kernel,
                         cudaFuncAttributeMaxDynamicSharedMemorySize,
                         2 * PROJ_STAGE_W * 4);

    split_kernel<<<(XN4 + WQ4 + WP4 + 255) / 256, 256>>>(x, w_qkv, w_proj);

    dim3 g1(NT / 128, O3 / 64, BATCH);
    qkv_tc_kernel<<<g1, 256, 2 * QKV_STAGE_W * 4>>>(b_qkv);

    dim3 g2(NT / MT, BATCH * NH);
    attn_mma_kernel<<<g2, 256, ATT_SMEM>>>();

    dim3 g3(NT / 128, CCH / 64, BATCH);
    proj_tc_kernel<<<g3, 256, 2 * PROJ_STAGE_W * 4>>>(b_proj, out);
}

// round 13
// speedup vs baseline: 2.4180x; 1.2759x over previous
#include <cuda_runtime.h>
#include <cuda_fp16.h>
#include <cstdint>

// Problem constants
#define BATCH 4
#define CCH   256
#define NH    8
#define DH    32
#define NT    2304
#define O3    768
#define MT    256
#define KT    128
#define NTILE (NT / KT)    // 18

// Scratch (allocation-free rule: __device__ globals)
__device__ __half g_qh [BATCH * NH * NT * DH];  // fp16, scaled by dh^-.5*log2e
__device__ __half g_kh [BATCH * NH * NT * DH];
__device__ __half g_vh [BATCH * NH * NT * DH];
__device__ __half g_aoh[BATCH * NT * CCH];      // attention out, fp16
__device__ __half g_xh [BATCH * CCH * NT];      // x, fp16
__device__ __half g_wqh[O3 * CCH];              // w_qkv, fp16
__device__ __half g_wph[CCH * CCH];             // w_proj, fp16

__device__ __forceinline__ float ex2f(float x) {
    float r;
    asm("ex2.approx.f32 %0, %1;" : "=f"(r) : "f"(x));
    return r;
}
__device__ __forceinline__ uint32_t pack_h2(float lo, float hi) {
    uint32_t r;
    asm("cvt.rn.f16x2.f32 %0, %1, %2;" : "=r"(r) : "f"(hi), "f"(lo));
    return r;
}
__device__ __forceinline__ uint32_t smem_u32(const void* p) {
    uint32_t a;
    asm("{ .reg .u64 t; cvta.to.shared.u64 t, %1; cvt.u32.u64 %0, t; }" : "=r"(a) : "l"(p));
    return a;
}
__device__ __forceinline__ void cp16(uint32_t dst, const void* src) {
    asm volatile("cp.async.cg.shared.global [%0], [%1], 16;" :: "r"(dst), "l"(src));
}
#define CP_COMMIT() asm volatile("cp.async.commit_group;" ::: "memory")
#define CP_WAIT1()  asm volatile("cp.async.wait_group 1;" ::: "memory")
#define ONE_H2 0x3C003C00u

__device__ __forceinline__ void mma_f16(float c[4], const uint32_t a[4],
                                        uint32_t b0, uint32_t b1) {
    asm volatile(
        "mma.sync.aligned.m16n8k16.row.col.f32.f16.f16.f32 "
        "{%0,%1,%2,%3}, {%4,%5,%6,%7}, {%8,%9}, {%0,%1,%2,%3};"
        : "+f"(c[0]), "+f"(c[1]), "+f"(c[2]), "+f"(c[3])
        : "r"(a[0]), "r"(a[1]), "r"(a[2]), "r"(a[3]), "r"(b0), "r"(b1));
}
__device__ __forceinline__ void ldsm4t(uint32_t& r0, uint32_t& r1,
                                       uint32_t& r2, uint32_t& r3, uint32_t addr) {
    asm volatile(
        "ldmatrix.sync.aligned.m8n8.x4.trans.shared.b16 {%0,%1,%2,%3}, [%4];"
        : "=r"(r0), "=r"(r1), "=r"(r2), "=r"(r3) : "r"(addr));
}

// ---------------------------------------------------------------------------
// Kernel 0: prep — convert x, w_qkv, w_proj to fp16.
// ---------------------------------------------------------------------------
#define XN4 (BATCH * CCH * NT / 4)
#define WQ4 (O3 * CCH / 4)
#define WP4 (CCH * CCH / 4)

__global__ __launch_bounds__(256) void split_kernel(
    const float* __restrict__ x, const float* __restrict__ wq,
    const float* __restrict__ wp)
{
    int i = blockIdx.x * 256 + threadIdx.x;
    const float4* src;
    uint2* dst;
    int j;
    if (i < XN4)                  { src = (const float4*)x;  dst = (uint2*)g_xh;  j = i; }
    else if (i < XN4 + WQ4)       { src = (const float4*)wq; dst = (uint2*)g_wqh; j = i - XN4; }
    else if (i < XN4 + WQ4 + WP4) { src = (const float4*)wp; dst = (uint2*)g_wph; j = i - XN4 - WQ4; }
    else return;
    float4 f = src[j];
    dst[j] = make_uint2(pack_h2(f.x, f.y), pack_h2(f.z, f.w));
}

// ---------------------------------------------------------------------------
// Kernel 1: QKV projection, fp16 m16n8k16 GEMM, BK=32, cp.async 2-stage.
//   A = x [k][m] staged (m-contiguous), stride 136 halves (17x16B, odd ->
//   ldmatrix conflict-free); A-frags via ldmatrix.x4.trans. B = w [n][k],
//   stride 40 halves, direct 32-bit frag loads.
//   Stage: A 32x136h (8704 B) + B 64x40h (5120 B) = 13824 B.
// ---------------------------------------------------------------------------
#define QKV_STAGE_B 13824

__global__ __launch_bounds__(256, 3) void qkv_tc_kernel(const float* __restrict__ bias)
{
    extern __shared__ __half sh[];
    const uint32_t sb = smem_u32(sh);

    const int b  = blockIdx.z;
    const int m0 = blockIdx.x * 128;
    const int o0 = blockIdx.y * 64;
    const int tid  = threadIdx.x;
    const int wid  = tid >> 5;
    const int lane = tid & 31;
    const int gq   = lane >> 2;
    const int t4   = lane & 3;
    const int wm   = wid & 3, wn = wid >> 2;

    // staging coords
    const int arow = tid >> 3, acol = (tid & 7) * 16;   // A: 32 rows x 128 halves
    const int brow = tid >> 2, bcol = (tid & 3) * 8;    // B: 64 rows x 32 halves

    const __half* xh = g_xh + (size_t)b * CCH * NT;
    const uint32_t a_off = (uint32_t)(arow * 136 + acol) * 2;
    const uint32_t b_off = 8704u + (uint32_t)(brow * 40 + bcol) * 2;

    // ldmatrix lane address pieces: k_l = (lane&7) + 8*(lane>=16), m_l = 8*((lane>>3)&1)
    const int k_l = (lane & 7) + ((lane >> 4) << 3);
    const int m_l = ((lane >> 3) & 1) * 8;

    {
        const __half* as = xh + (size_t)arow * NT + m0 + acol;
        cp16(sb + a_off,      as);
        cp16(sb + a_off + 16, as + 8);
        cp16(sb + b_off, g_wqh + (size_t)(o0 + brow) * CCH + bcol);
    }
    CP_COMMIT();

    float c[2][4][4] = {};

    for (int it = 0; it < 8; it++) {
        if (it + 1 < 8) {
            const int k0 = (it + 1) * 32;
            const uint32_t base = sb + ((it + 1) & 1) * QKV_STAGE_B;
            const __half* as = xh + (size_t)(k0 + arow) * NT + m0 + acol;
            cp16(base + a_off,      as);
            cp16(base + a_off + 16, as + 8);
            cp16(base + b_off, g_wqh + (size_t)(o0 + brow) * CCH + k0 + bcol);
        }
        CP_COMMIT();
        CP_WAIT1();
        __syncthreads();

        const uint32_t Ab = sb + (it & 1) * QKV_STAGE_B;
        const __half* Bp = sh + ((it & 1) * QKV_STAGE_B + 8704) / 2;

        #pragma unroll
        for (int kc = 0; kc < 2; kc++) {
            uint32_t af[2][4];
            #pragma unroll
            for (int mt = 0; mt < 2; mt++) {
                uint32_t addr = Ab + (uint32_t)((kc * 16 + k_l) * 136
                                 + wm * 32 + mt * 16 + m_l) * 2;
                ldsm4t(af[mt][0], af[mt][1], af[mt][2], af[mt][3], addr);
            }
            #pragma unroll
            for (int nt = 0; nt < 4; nt++) {
                int n = wn * 32 + nt * 8 + gq;
                const __half* bp = Bp + n * 40 + kc * 16 + 2 * t4;
                uint32_t b0 = *(const uint32_t*)bp;
                uint32_t b1 = *(const uint32_t*)(bp + 8);
                mma_f16(c[0][nt], af[0], b0, b1);
                mma_f16(c[1][nt], af[1], b0, b1);
            }
        }
        __syncthreads();
    }

    // epilogue: bias; q scaled by dh^-0.5 * log2(e); fp16 outputs
    const float scale = 0.25503487f;
    #pragma unroll
    for (int mt = 0; mt < 2; mt++)
        #pragma unroll
        for (int nt = 0; nt < 4; nt++)
            #pragma unroll
            for (int i = 0; i < 4; i++) {
                int m = m0 + wm * 32 + mt * 16 + gq + ((i >= 2) ? 8 : 0);
                int o = o0 + wn * 32 + nt * 8 + 2 * t4 + (i & 1);
                float val = c[mt][nt][i] + __ldg(bias + o);
                int kind = o / CCH;
                int oc = o % CCH;
                int h = oc / DH, d = oc % DH;
                int idx = ((b * NH + h) * NT + m) * DH + d;
                if (kind == 0)
                    g_qh[idx] = __float2half_rn(val * scale);
                else if (kind == 1)
                    g_kh[idx] = __float2half_rn(val);
                else
                    g_vh[idx] = __float2half_rn(val);
            }
}

// ---------------------------------------------------------------------------
// Kernel 2: fp16 m16n8k16 flash attention, MT=256 (unchanged loop from R12;
//   epilogue now writes g_aoh as fp16 pairs).
// ---------------------------------------------------------------------------
#define KSTR_H 40
#define STAGE_HALVES (2 * KT * KSTR_H)
#define ATT_STAGE_B  (STAGE_HALVES * 2)
#define ATT_SMEM     (2 * ATT_STAGE_B)

__global__ __launch_bounds__(256, 2) void attn_mma_kernel()
{
    extern __shared__ __half smh[];
    const uint32_t smbase = smem_u32(smh);

    const int bh   = blockIdx.y;
    const int n0   = blockIdx.x * MT;
    const int tid  = threadIdx.x;
    const int wid  = tid >> 5;
    const int lane = tid & 31;
    const int gq   = lane >> 2;
    const int t4   = lane & 3;
    const int r0   = wid * 32 + gq;

    const int srow = tid >> 1;
    const int shalf = tid & 1;
    const __half* kbase = g_kh + ((size_t)bh * NT + srow) * DH + shalf * 16;
    const __half* vbase = g_vh + ((size_t)bh * NT + srow) * DH + shalf * 16;
    const uint32_t kdst_off = (uint32_t)(srow * KSTR_H + shalf * 16) * 2;
    const uint32_t vdst_off = kdst_off + KT * KSTR_H * 2;

    const uint32_t lrow = lane & 15;
    const uint32_t lhof = (lane >> 4) * 8;

    uint32_t qa[2][2][4];
    #pragma unroll
    for (int mt = 0; mt < 2; mt++) {
        const __half* Q0 = g_qh + ((size_t)bh * NT + n0 + r0 + mt * 16) * DH;
        const __half* Q8 = Q0 + 8 * DH;
        #pragma unroll
        for (int kc = 0; kc < 2; kc++) {
            qa[mt][kc][0] = *(const uint32_t*)(Q0 + 2 * t4 + 16 * kc);
            qa[mt][kc][1] = *(const uint32_t*)(Q8 + 2 * t4 + 16 * kc);
            qa[mt][kc][2] = *(const uint32_t*)(Q0 + 2 * t4 + 8 + 16 * kc);
            qa[mt][kc][3] = *(const uint32_t*)(Q8 + 2 * t4 + 8 + 16 * kc);
        }
    }

    float o[2][4][4] = {};
    float la[2][4] = {};

    {
        #pragma unroll
        for (int cv = 0; cv < 2; cv++) {
            cp16(smbase + kdst_off + cv * 16, kbase + cv * 8);
            cp16(smbase + vdst_off + cv * 16, vbase + cv * 8);
        }
    }
    CP_COMMIT();

    for (int t = 0; t < NTILE; t++) {
        if (t + 1 < NTILE) {
            const uint32_t base = smbase + ((t + 1) & 1) * ATT_STAGE_B;
            const __half* ks = kbase + (size_t)(t + 1) * KT * DH;
            const __half* vs = vbase + (size_t)(t + 1) * KT * DH;
            #pragma unroll
            for (int cv = 0; cv < 2; cv++) {
                cp16(base + kdst_off + cv * 16, ks + cv * 8);
                cp16(base + vdst_off + cv * 16, vs + cv * 8);
            }
        }
        CP_COMMIT();
        CP_WAIT1();
        __syncthreads();

        const __half* Ksp = smh + (t & 1) * STAGE_HALVES;
        const uint32_t vsm = smbase + (t & 1) * ATT_STAGE_B + KT * KSTR_H * 2;

        #pragma unroll 2
        for (int c = 0; c < 8; c++) {
            uint32_t kb[2][2][2];
            #pragma unroll
            for (int g = 0; g < 2; g++) {
                const __half* kr = Ksp + (c * 16 + 8 * g + gq) * KSTR_H + 2 * t4;
                #pragma unroll
                for (int kc = 0; kc < 2; kc++) {
                    kb[g][kc][0] = *(const uint32_t*)(kr + 16 * kc);
                    kb[g][kc][1] = *(const uint32_t*)(kr + 16 * kc + 8);
                }
            }
            float s[2][2][4] = {};
            #pragma unroll
            for (int g = 0; g < 2; g++)
                #pragma unroll
                for (int mt = 0; mt < 2; mt++) {
                    mma_f16(s[g][mt], qa[mt][0], kb[g][0][0], kb[g][0][1]);
                    mma_f16(s[g][mt], qa[mt][1], kb[g][1][0], kb[g][1][1]);
                }
            uint32_t pa[2][4];
            #pragma unroll
            for (int mt = 0; mt < 2; mt++) {
                pa[mt][0] = pack_h2(ex2f(s[0][mt][0]), ex2f(s[0][mt][1]));
                pa[mt][1] = pack_h2(ex2f(s[0][mt][2]), ex2f(s[0][mt][3]));
                pa[mt][2] = pack_h2(ex2f(s[1][mt][0]), ex2f(s[1][mt][1]));
                pa[mt][3] = pack_h2(ex2f(s[1][mt][2]), ex2f(s[1][mt][3]));
            }
            mma_f16(la[0], pa[0], ONE_H2, ONE_H2);
            mma_f16(la[1], pa[1], ONE_H2, ONE_H2);
            uint32_t vb[4][2];
            uint32_t va = vsm + ((c * 16 + lrow) * KSTR_H + lhof) * 2;
            ldsm4t(vb[0][0], vb[0][1], vb[1][0], vb[1][1], va);
            ldsm4t(vb[2][0], vb[2][1], vb[3][0], vb[3][1], va + 32);
            #pragma unroll
            for (int mt = 0; mt < 2; mt++)
                #pragma unroll
                for (int db = 0; db < 4; db++)
                    mma_f16(o[mt][db], pa[mt], vb[db][0], vb[db][1]);
        }
        __syncthreads();
    }

    // finalize: normalize; write g_aoh fp16 (pairs are d-adjacent)
    const int b = bh >> 3, h = bh & 7;
    #pragma unroll
    for (int mt = 0; mt < 2; mt++) {
        float i0 = 1.f / la[mt][0];
        float i1 = 1.f / la[mt][2];
        size_t off0 = ((size_t)(b * NT) + n0 + r0 + mt * 16) * CCH + h * DH;
        size_t off8 = off0 + 8 * CCH;
        #pragma unroll
        for (int db = 0; db < 4; db++) {
            int d = db * 8 + 2 * t4;
            *(uint32_t*)(g_aoh + off0 + d) =
                pack_h2(o[mt][db][0] * i0, o[mt][db][1] * i0);
            *(uint32_t*)(g_aoh + off8 + d) =
                pack_h2(o[mt][db][2] * i1, o[mt][db][3] * i1);
        }
    }
}

// ---------------------------------------------------------------------------
// Kernel 3: output projection, fp16 m16n8k16 GEMM, BK=32, cp.async 2-stage.
//   A = g_aoh [m][k] k-contig (direct frag loads), B = w_proj [n][k].
//   Both strides 40 halves (conflict-free). Stage: A 128x40h + B 64x40h
//   = 15360 B.
// ---------------------------------------------------------------------------
#define PROJ_STAGE_B 15360

__global__ __launch_bounds__(256, 3) void proj_tc_kernel(
    const float* __restrict__ bias, float* __restrict__ out)
{
    extern __shared__ __half ph[];
    const uint32_t sb = smem_u32(ph);

    const int b  = blockIdx.z;
    const int m0 = blockIdx.x * 128;
    const int o0 = blockIdx.y * 64;
    const int tid  = threadIdx.x;
    const int wid  = tid >> 5;
    const int lane = tid & 31;
    const int gq   = lane >> 2;
    const int t4   = lane & 3;
    const int wm   = wid & 3, wn = wid >> 2;

    const int arow = tid >> 1, acol = (tid & 1) * 16;   // A: 128 rows x 32 halves
    const int brow = tid >> 2, bcol = (tid & 3) * 8;    // B: 64 rows x 32 halves

    const __half* ag = g_aoh + (size_t)b * NT * CCH;
    const uint32_t a_off = (uint32_t)(arow * 40 + acol) * 2;
    const uint32_t b_off = 10240u + (uint32_t)(brow * 40 + bcol) * 2;

    {
        const __half* as = ag + (size_t)(m0 + arow) * CCH + acol;
        cp16(sb + a_off,      as);
        cp16(sb + a_off + 16, as + 8);
        cp16(sb + b_off, g_wph + (size_t)(o0 + brow) * CCH + bcol);
    }
    CP_COMMIT();

    float c[2][4][4] = {};

    for (int it = 0; it < 8; it++) {
        if (it + 1 < 8) {
            const int k0 = (it + 1) * 32;
            const uint32_t base = sb + ((it + 1) & 1) * PROJ_STAGE_B;
            const __half* as = ag + (size_t)(m0 + arow) * CCH + k0 + acol;
            cp16(base + a_off,      as);
            cp16(base + a_off + 16, as + 8);
            cp16(base + b_off, g_wph + (size_t)(o0 + brow) * CCH + k0 + bcol);
        }
        CP_COMMIT();
        CP_WAIT1();
        __syncthreads();

        const __half* Ap = ph + ((it & 1) * PROJ_STAGE_B) / 2;
        const __half* Bp = Ap + 5120;

        #pragma unroll
        for (int kc = 0; kc < 2; kc++) {
            uint32_t af[2][4];
            #pragma unroll
            for (int mt = 0; mt < 2; mt++) {
                int m = wm * 32 + mt * 16 + gq;
                const __half* ar = Ap + m * 40 + kc * 16 + 2 * t4;
                af[mt][0] = *(const uint32_t*)ar;
                af[mt][1] = *(const uint32_t*)(ar + 8 * 40);
                af[mt][2] = *(const uint32_t*)(ar + 8);
                af[mt][3] = *(const uint32_t*)(ar + 8 * 40 + 8);
            }
            #pragma unroll
            for (int nt = 0; nt < 4; nt++) {
                int n = wn * 32 + nt * 8 + gq;
                const __half* bp = Bp + n * 40 + kc * 16 + 2 * t4;
                uint32_t b0 = *(const uint32_t*)bp;
                uint32_t b1 = *(const uint32_t*)(bp + 8);
                mma_f16(c[0][nt], af[0], b0, b1);
                mma_f16(c[1][nt], af[1], b0, b1);
            }
        }
        __syncthreads();
    }

    #pragma unroll
    for (int mt = 0; mt < 2; mt++)
        #pragma unroll
        for (int nt = 0; nt < 4; nt++)
            #pragma unroll
            for (int i = 0; i < 4; i++) {
                int m = m0 + wm * 32 + mt * 16 + gq + ((i >= 2) ? 8 : 0);
                int o = o0 + wn * 32 + nt * 8 + 2 * t4 + (i & 1);
                out[(size_t)b * CCH * NT + (size_t)o * NT + m] =
                    c[mt][nt][i] + __ldg(bias + o);
            }
}

// ---------------------------------------------------------------------------
extern "C" void kernel_launch(void* const* d_in, const int* in_sizes, int n_in,
                              void* d_out, int out_size)
{
    (void)in_sizes; (void)n_in; (void)out_size;
    const float* x      = (const float*)d_in[0];
    const float* w_qkv  = (const float*)d_in[1];
    const float* b_qkv  = (const float*)d_in[2];
    const float* w_proj = (const float*)d_in[3];
    const float* b_proj = (const float*)d_in[4];
    float* out = (float*)d_out;

    cudaFuncSetAttribute(qkv_tc_kernel,
                         cudaFuncAttributeMaxDynamicSharedMemorySize,
                         2 * QKV_STAGE_B);
    cudaFuncSetAttribute(attn_mma_kernel,
                         cudaFuncAttributeMaxDynamicSharedMemorySize, ATT_SMEM);
    cudaFuncSetAttribute(proj_tc_kernel,
                         cudaFuncAttributeMaxDynamicSharedMemorySize,
                         2 * PROJ_STAGE_B);

    split_kernel<<<(XN4 + WQ4 + WP4 + 255) / 256, 256>>>(x, w_qkv, w_proj);

    dim3 g1(NT / 128, O3 / 64, BATCH);
    qkv_tc_kernel<<<g1, 256, 2 * QKV_STAGE_B>>>(b_qkv);

    dim3 g2(NT / MT, BATCH * NH);
    attn_mma_kernel<<<g2, 256, ATT_SMEM>>>();

    dim3 g3(NT / 128, CCH / 64, BATCH);
    proj_tc_kernel<<<g3, 256, 2 * PROJ_STAGE_B>>>(b_proj, out);
}